// round 1
// baseline (speedup 1.0000x reference)
#include <cuda_runtime.h>

// ---------------- static scratch (allocation-free rule: __device__ globals) ----
__device__ float g_sum[1024];
__device__ float g_sumsq[1024];
__device__ float g_mean[1024];
__device__ float g_rstd[1024];

__device__ float s_h1[8192 * 64];
__device__ float s_h2[8192 * 256];
__device__ float s_lA[8192 * 512];
__device__ int   s_idx[8192 * 8];
__device__ float s_bufA[67108864];   // 65536 x 1024 (reused at stride 512 for stage A)
__device__ float s_bufB[67108864];

// ---------------- layer 1: xyz(8192x3) @ W1^T(3x64) -------------------------
__global__ void gemm_k3(const float* __restrict__ xyz, const float* __restrict__ W,
                        float* __restrict__ out) {
    int i = blockIdx.x * 256 + threadIdx.x;          // 8192*64
    if (i >= 8192 * 64) return;
    int o = i & 63;
    int m = i >> 6;
    const float* x = xyz + m * 3;
    const float* w = W + o * 3;
    out[i] = x[0] * w[0] + x[1] * w[1] + x[2] * w[2];
}

// ---------------- generic NT SGEMM: C[M,N] = A[M,K] * B[N,K]^T ---------------
// requires M%128==0, N%128==0, K%8==0
__global__ void __launch_bounds__(256) sgemm_nt(const float* __restrict__ A,
                                                const float* __restrict__ Bm,
                                                float* __restrict__ C,
                                                int M, int N, int K) {
    __shared__ float As[8][128];
    __shared__ float Bs[8][128];
    const int bm = blockIdx.y * 128;
    const int bn = blockIdx.x * 128;
    const int tid = threadIdx.x;
    const int lrow = tid >> 1;            // 0..127
    const int lcol = (tid & 1) << 2;      // 0 or 4
    const int ty = tid >> 4;              // 0..15
    const int tx = tid & 15;              // 0..15

    float acc[8][8];
#pragma unroll
    for (int i = 0; i < 8; i++)
#pragma unroll
        for (int j = 0; j < 8; j++) acc[i][j] = 0.f;

    const float* Aptr = A + (size_t)(bm + lrow) * K + lcol;
    const float* Bptr = Bm + (size_t)(bn + lrow) * K + lcol;

    for (int k0 = 0; k0 < K; k0 += 8) {
        float4 av = *(const float4*)(Aptr + k0);
        float4 bv = *(const float4*)(Bptr + k0);
        As[lcol + 0][lrow] = av.x; As[lcol + 1][lrow] = av.y;
        As[lcol + 2][lrow] = av.z; As[lcol + 3][lrow] = av.w;
        Bs[lcol + 0][lrow] = bv.x; Bs[lcol + 1][lrow] = bv.y;
        Bs[lcol + 2][lrow] = bv.z; Bs[lcol + 3][lrow] = bv.w;
        __syncthreads();
#pragma unroll
        for (int kk = 0; kk < 8; kk++) {
            float ar[8], br[8];
            *(float4*)&ar[0] = *(const float4*)&As[kk][ty * 8];
            *(float4*)&ar[4] = *(const float4*)&As[kk][ty * 8 + 4];
            *(float4*)&br[0] = *(const float4*)&Bs[kk][tx * 8];
            *(float4*)&br[4] = *(const float4*)&Bs[kk][tx * 8 + 4];
#pragma unroll
            for (int i = 0; i < 8; i++)
#pragma unroll
                for (int j = 0; j < 8; j++) acc[i][j] = fmaf(ar[i], br[j], acc[i][j]);
        }
        __syncthreads();
    }
#pragma unroll
    for (int i = 0; i < 8; i++) {
        float* Cp = C + (size_t)(bm + ty * 8 + i) * N + bn + tx * 8;
        float4 v0 = {acc[i][0], acc[i][1], acc[i][2], acc[i][3]};
        float4 v1 = {acc[i][4], acc[i][5], acc[i][6], acc[i][7]};
        *(float4*)Cp = v0;
        *(float4*)(Cp + 4) = v1;
    }
}

// ---------------- batchnorm: stats + finalize + apply ------------------------
__global__ void zero_stats() {
    g_sum[threadIdx.x] = 0.f;
    g_sumsq[threadIdx.x] = 0.f;
}

__global__ void bn_stats(const float* __restrict__ x, int rpb, int C) {
    int c = threadIdx.x;                          // blockDim == C
    const float* p = x + (size_t)blockIdx.x * rpb * C + c;
    float s = 0.f, ss = 0.f;
    for (int r = 0; r < rpb; r++) {
        float v = p[(size_t)r * C];
        s += v;
        ss += v * v;
    }
    atomicAdd(&g_sum[c], s);
    atomicAdd(&g_sumsq[c], ss);
}

__global__ void bn_finalize(float inv_n) {
    int c = threadIdx.x;
    float m = g_sum[c] * inv_n;
    float v = g_sumsq[c] * inv_n - m * m;
    g_mean[c] = m;
    g_rstd[c] = rsqrtf(v + 1e-5f);
}

__global__ void bn_apply(float* __restrict__ x, const float* __restrict__ gg,
                         const float* __restrict__ bb, int total, int cmask) {
    int i = blockIdx.x * 256 + threadIdx.x;
    if (i >= total) return;
    int c = i & cmask;
    float v = (x[i] - g_mean[c]) * g_rstd[c] * gg[c] + bb[c];
    x[i] = fmaxf(v, 0.f);
}

// bn + relu + max over the 8 grouped neighbors -> lA[bn, c]
__global__ void bn_apply_maxpool(const float* __restrict__ pre, const float* __restrict__ gg,
                                 const float* __restrict__ bb, float* __restrict__ out,
                                 int clog, int total) {
    int i = blockIdx.x * 256 + threadIdx.x;       // over 8192 * C
    if (i >= total) return;
    int c = i & ((1 << clog) - 1);
    int bn = i >> clog;
    float m = g_mean[c], r = g_rstd[c] * gg[c], be = bb[c];
    const float* p = pre + (((size_t)bn * 8) << clog) + c;
    float best = 0.f;                             // relu folds into 0-init max
#pragma unroll
    for (int k = 0; k < 8; k++) {
        float v = (p[(size_t)k << clog] - m) * r + be;
        best = fmaxf(best, v);
    }
    out[i] = best;
}

// same, final layer: writes transposed output out[b, c, n]
__global__ void bn_apply_maxpool_T(const float* __restrict__ pre, const float* __restrict__ gg,
                                   const float* __restrict__ bb, float* __restrict__ out) {
    int i = blockIdx.x * 256 + threadIdx.x;       // 8192 * 1024
    if (i >= 8192 * 1024) return;
    int c = i & 1023;
    int bn = i >> 10;                             // b*1024 + n
    int b = bn >> 10, n = bn & 1023;
    float m = g_mean[c], r = g_rstd[c] * gg[c], be = bb[c];
    const float* p = pre + (((size_t)bn * 8) << 10) + c;
    float best = 0.f;
#pragma unroll
    for (int k = 0; k < 8; k++) {
        float v = (p[(size_t)k << 10] - m) * r + be;
        best = fmaxf(best, v);
    }
    out[((((size_t)b << 10) | c) << 10) | n] = best;
}

// ---------------- kNN (k=8, includes self at d2==0) --------------------------
// d2 = (sq_i + sq_j) - 2*dot  -- exact same formula as reference.
// Only the neighbor SET matters (max-pool downstream), so ordering is free.
__global__ void knn_kernel(const float* __restrict__ xyz, int* __restrict__ idx) {
    __shared__ float sx[1024], sy[1024], sz[1024], ssq[1024];
    int b = blockIdx.y;
    const float* base = xyz + b * 1024 * 3;
    for (int i = threadIdx.x; i < 1024; i += blockDim.x) {
        float x = base[i * 3 + 0], y = base[i * 3 + 1], z = base[i * 3 + 2];
        sx[i] = x; sy[i] = y; sz[i] = z;
        ssq[i] = x * x + y * y + z * z;
    }
    __syncthreads();
    int n = blockIdx.x * blockDim.x + threadIdx.x;
    float px = sx[n], py = sy[n], pz = sz[n], psq = ssq[n];
    float bd[8]; int bi[8];
#pragma unroll
    for (int s = 0; s < 8; s++) { bd[s] = 3.4e38f; bi[s] = 0; }
    int maxslot = 0;
    float worst = 3.4e38f;
    for (int j = 0; j < 1024; j++) {
        float d = (psq + ssq[j]) - 2.f * (px * sx[j] + py * sy[j] + pz * sz[j]);
        if (d < worst) {
#pragma unroll
            for (int s = 0; s < 8; s++) if (s == maxslot) { bd[s] = d; bi[s] = j; }
            worst = bd[0]; maxslot = 0;
#pragma unroll
            for (int s = 1; s < 8; s++) if (bd[s] > worst) { worst = bd[s]; maxslot = s; }
        }
    }
    int o = (b * 1024 + n) * 8;
#pragma unroll
    for (int s = 0; s < 8; s++) idx[o + s] = bi[s];
}

// ---------------- gather + concat: [feat[j]-feat[n], feat[n]] ----------------
__global__ void gather_concat(const float* __restrict__ feat, const int* __restrict__ idx,
                              float* __restrict__ out, int Cin, int coutShift, int total) {
    int i = blockIdx.x * 256 + threadIdx.x;
    if (i >= total) return;
    int c = i & ((1 << coutShift) - 1);
    int row = i >> coutShift;           // (b*1024+n)*8 + k
    int bn = row >> 3;
    int b = bn >> 10;
    float v;
    if (c < Cin) {
        int j = idx[row];
        v = feat[(size_t)((b << 10) + j) * Cin + c] - feat[(size_t)bn * Cin + c];
    } else {
        v = feat[(size_t)bn * Cin + (c - Cin)];
    }
    out[i] = v;
}

// ---------------- orchestration ---------------------------------------------
extern "C" void kernel_launch(void* const* d_in, const int* in_sizes, int n_in,
                              void* d_out, int out_size) {
    const float* xyz = (const float*)d_in[0];
    const float* W1  = (const float*)d_in[1];
    const float* g1  = (const float*)d_in[2];
    const float* b1  = (const float*)d_in[3];
    const float* W2  = (const float*)d_in[4];
    const float* g2  = (const float*)d_in[5];
    const float* b2  = (const float*)d_in[6];
    const float* WA1 = (const float*)d_in[7];
    const float* gA1 = (const float*)d_in[8];
    const float* bA1 = (const float*)d_in[9];
    const float* WA2 = (const float*)d_in[10];
    const float* gA2 = (const float*)d_in[11];
    const float* bA2 = (const float*)d_in[12];
    const float* WB1 = (const float*)d_in[13];
    const float* gB1 = (const float*)d_in[14];
    const float* bB1 = (const float*)d_in[15];
    const float* WB2 = (const float*)d_in[16];
    const float* gB2 = (const float*)d_in[17];
    const float* bB2 = (const float*)d_in[18];
    float* out = (float*)d_out;

    float *h1, *h2, *lA, *bufA, *bufB;
    int* idx;
    cudaGetSymbolAddress((void**)&h1,   s_h1);
    cudaGetSymbolAddress((void**)&h2,   s_h2);
    cudaGetSymbolAddress((void**)&lA,   s_lA);
    cudaGetSymbolAddress((void**)&bufA, s_bufA);
    cudaGetSymbolAddress((void**)&bufB, s_bufB);
    cudaGetSymbolAddress((void**)&idx,  s_idx);

    // ---- layer 1: 3 -> 64, BN+ReLU (stats over 8192 rows)
    gemm_k3<<<(8192 * 64) / 256, 256>>>(xyz, W1, h1);
    zero_stats<<<1, 1024>>>();
    bn_stats<<<8192 / 32, 64>>>(h1, 32, 64);
    bn_finalize<<<1, 64>>>(1.f / 8192);
    bn_apply<<<(8192 * 64) / 256, 256>>>(h1, g1, b1, 8192 * 64, 63);

    // ---- layer 2: 64 -> 256, BN+ReLU
    sgemm_nt<<<dim3(256 / 128, 8192 / 128), 256>>>(h1, W2, h2, 8192, 256, 64);
    zero_stats<<<1, 1024>>>();
    bn_stats<<<8192 / 32, 256>>>(h2, 32, 256);
    bn_finalize<<<1, 256>>>(1.f / 8192);
    bn_apply<<<(8192 * 256) / 256, 256>>>(h2, g2, b2, 8192 * 256, 255);

    // ---- kNN on xyz (shared by both group stages)
    knn_kernel<<<dim3(4, 8), 256>>>(xyz, idx);

    // ---- group A: h2 (C=256) -> bufA rows 65536 x 512
    gather_concat<<<(65536 * 512) / 256, 256>>>(h2, idx, bufA, 256, 9, 65536 * 512);

    // ---- A1: 512 -> 512, BN+ReLU (stats over 65536 rows)
    sgemm_nt<<<dim3(512 / 128, 65536 / 128), 256>>>(bufA, WA1, bufB, 65536, 512, 512);
    zero_stats<<<1, 1024>>>();
    bn_stats<<<65536 / 64, 512>>>(bufB, 64, 512);
    bn_finalize<<<1, 512>>>(1.f / 65536);
    bn_apply<<<(65536 * 512) / 256, 256>>>(bufB, gA1, bA1, 65536 * 512, 511);

    // ---- A2: 512 -> 512, BN+ReLU+maxpool(k) -> lA (8192 x 512)
    sgemm_nt<<<dim3(4, 512), 256>>>(bufB, WA2, bufA, 65536, 512, 512);
    zero_stats<<<1, 1024>>>();
    bn_stats<<<65536 / 64, 512>>>(bufA, 64, 512);
    bn_finalize<<<1, 512>>>(1.f / 65536);
    bn_apply_maxpool<<<(8192 * 512) / 256, 256>>>(bufA, gA2, bA2, lA, 9, 8192 * 512);

    // ---- group B: lA (C=512) -> bufB rows 65536 x 1024
    gather_concat<<<(65536 * 1024) / 256, 256>>>(lA, idx, bufB, 512, 10, 65536 * 1024);

    // ---- B1: 1024 -> 1024, BN+ReLU
    sgemm_nt<<<dim3(8, 512), 256>>>(bufB, WB1, bufA, 65536, 1024, 1024);
    zero_stats<<<1, 1024>>>();
    bn_stats<<<65536 / 64, 1024>>>(bufA, 64, 1024);
    bn_finalize<<<1, 1024>>>(1.f / 65536);
    bn_apply<<<(65536 * 1024) / 256, 256>>>(bufA, gB1, bB1, 65536 * 1024, 1023);

    // ---- B2: 1024 -> 1024, BN+ReLU+maxpool(k), transposed write to d_out
    sgemm_nt<<<dim3(8, 512), 256>>>(bufA, WB2, bufB, 65536, 1024, 1024);
    zero_stats<<<1, 1024>>>();
    bn_stats<<<65536 / 64, 1024>>>(bufB, 64, 1024);
    bn_finalize<<<1, 1024>>>(1.f / 65536);
    bn_apply_maxpool_T<<<(8192 * 1024) / 256, 256>>>(bufB, gB2, bB2, out);
}

// round 3
// speedup vs baseline: 2.3714x; 2.3714x over previous
#include <cuda_runtime.h>
#include <cstdint>

// ---------------- static scratch (allocation-free rule: __device__ globals) ----
__device__ float g_sum[1024];
__device__ float g_sumsq[1024];
__device__ float g_mean[1024];
__device__ float g_rstd[1024];

__device__ float s_h1[8192 * 64];
__device__ float s_h2[8192 * 256];
__device__ float s_lA[8192 * 512];
__device__ int   s_idx[8192 * 8];
__device__ float s_uv[8192 * 2048];     // U|V combined GEMM output
__device__ float s_wcat[2048 * 512];    // [WL ; WR-WL]
__device__ float s_bufA[67108864];      // 65536 x 1024 max
__device__ float s_bufB[67108864];

// ================= 3xTF32 split-precision tensor-core NT GEMM ================
// C[M,N] = A[M,K] * B[N,K]^T ; M%128==0, N%128==0, K%16==0 ; ~fp32 accuracy
__device__ __forceinline__ void cp16(uint32_t dst, const void* src) {
    asm volatile("cp.async.ca.shared.global [%0], [%1], 16;\n" :: "r"(dst), "l"(src));
}
__device__ __forceinline__ uint32_t f2tf(float f) {
    uint32_t r;
    asm("cvt.rna.tf32.f32 %0, %1;" : "=r"(r) : "f"(f));
    return r;
}
__device__ __forceinline__ void tf_split(float f, uint32_t& hi, uint32_t& lo) {
    hi = f2tf(f);
    lo = f2tf(f - __uint_as_float(hi));
}
__device__ __forceinline__ void mma8(float* d, const uint32_t* a, const uint32_t* b) {
    asm volatile(
        "mma.sync.aligned.m16n8k8.row.col.f32.tf32.tf32.f32 "
        "{%0,%1,%2,%3},{%4,%5,%6,%7},{%8,%9},{%0,%1,%2,%3};"
        : "+f"(d[0]), "+f"(d[1]), "+f"(d[2]), "+f"(d[3])
        : "r"(a[0]), "r"(a[1]), "r"(a[2]), "r"(a[3]), "r"(b[0]), "r"(b[1]));
}

__global__ void __launch_bounds__(256) gemm_tf32(const float* __restrict__ A,
                                                 const float* __restrict__ B,
                                                 float* __restrict__ C,
                                                 int M, int N, int K) {
    __shared__ float As[2][128][20];
    __shared__ float Bs[2][128][20];
    const int tid = threadIdx.x, lane = tid & 31, wid = tid >> 5;
    const int bm = blockIdx.y * 128, bn = blockIdx.x * 128;
    const int wm = (wid & 3) * 32, wn = (wid >> 2) * 64;
    const int lr = tid >> 2, lk = (tid & 3) << 2;

    const float* Ag = A + (size_t)(bm + lr) * K + lk;
    const float* Bg = B + (size_t)(bn + lr) * K + lk;

    float acc[2][8][4];
#pragma unroll
    for (int mi = 0; mi < 2; mi++)
#pragma unroll
        for (int ni = 0; ni < 8; ni++)
#pragma unroll
            for (int q = 0; q < 4; q++) acc[mi][ni][q] = 0.f;

    const int nk = K >> 4;
    cp16((uint32_t)__cvta_generic_to_shared(&As[0][lr][lk]),      Ag);
    cp16((uint32_t)__cvta_generic_to_shared(&As[0][lr + 64][lk]), Ag + (size_t)64 * K);
    cp16((uint32_t)__cvta_generic_to_shared(&Bs[0][lr][lk]),      Bg);
    cp16((uint32_t)__cvta_generic_to_shared(&Bs[0][lr + 64][lk]), Bg + (size_t)64 * K);
    asm volatile("cp.async.commit_group;\n" ::: "memory");

    for (int t = 0; t < nk; t++) {
        const int cur = t & 1, nxt = cur ^ 1;
        if (t + 1 < nk) {
            const float* Ap = Ag + (size_t)(t + 1) * 16;
            const float* Bp = Bg + (size_t)(t + 1) * 16;
            cp16((uint32_t)__cvta_generic_to_shared(&As[nxt][lr][lk]),      Ap);
            cp16((uint32_t)__cvta_generic_to_shared(&As[nxt][lr + 64][lk]), Ap + (size_t)64 * K);
            cp16((uint32_t)__cvta_generic_to_shared(&Bs[nxt][lr][lk]),      Bp);
            cp16((uint32_t)__cvta_generic_to_shared(&Bs[nxt][lr + 64][lk]), Bp + (size_t)64 * K);
        }
        asm volatile("cp.async.commit_group;\n" ::: "memory");
        asm volatile("cp.async.wait_group 1;\n" ::: "memory");
        __syncthreads();

#pragma unroll
        for (int ks = 0; ks < 2; ks++) {
            const int kk = ks * 8 + (lane & 3);
            uint32_t ah[2][4], al[2][4], bh[8][2], bl[8][2];
            const int ar = wm + (lane >> 2);
#pragma unroll
            for (int mi = 0; mi < 2; mi++) {
                tf_split(As[cur][ar + mi * 16][kk],         ah[mi][0], al[mi][0]);
                tf_split(As[cur][ar + mi * 16 + 8][kk],     ah[mi][1], al[mi][1]);
                tf_split(As[cur][ar + mi * 16][kk + 4],     ah[mi][2], al[mi][2]);
                tf_split(As[cur][ar + mi * 16 + 8][kk + 4], ah[mi][3], al[mi][3]);
            }
            const int br = wn + (lane >> 2);
#pragma unroll
            for (int ni = 0; ni < 8; ni++) {
                tf_split(Bs[cur][br + ni * 8][kk],     bh[ni][0], bl[ni][0]);
                tf_split(Bs[cur][br + ni * 8][kk + 4], bh[ni][1], bl[ni][1]);
            }
#pragma unroll
            for (int mi = 0; mi < 2; mi++)
#pragma unroll
                for (int ni = 0; ni < 8; ni++) {
                    mma8(acc[mi][ni], al[mi], bh[ni]);   // small terms first
                    mma8(acc[mi][ni], ah[mi], bl[ni]);
                    mma8(acc[mi][ni], ah[mi], bh[ni]);
                }
        }
        __syncthreads();
    }

#pragma unroll
    for (int mi = 0; mi < 2; mi++)
#pragma unroll
        for (int ni = 0; ni < 8; ni++) {
            const int r0 = bm + wm + mi * 16 + (lane >> 2);
            const int c0 = bn + wn + ni * 8 + ((lane & 3) << 1);
            *(float2*)&C[(size_t)r0 * N + c0]       = make_float2(acc[mi][ni][0], acc[mi][ni][1]);
            *(float2*)&C[(size_t)(r0 + 8) * N + c0] = make_float2(acc[mi][ni][2], acc[mi][ni][3]);
        }
}

// ---------------- layer 1: xyz(8192x3) @ W1^T(3x64) -------------------------
__global__ void gemm_k3(const float* __restrict__ xyz, const float* __restrict__ W,
                        float* __restrict__ out) {
    int i = blockIdx.x * 256 + threadIdx.x;
    if (i >= 8192 * 64) return;
    int o = i & 63;
    int m = i >> 6;
    const float* x = xyz + m * 3;
    const float* w = W + o * 3;
    out[i] = x[0] * w[0] + x[1] * w[1] + x[2] * w[2];
}

// ---------------- Wcat prep: out = [WL ; WR-WL] ------------------------------
__global__ void prep_wcat(const float* __restrict__ W, float* __restrict__ out,
                          int Cout, int Ch) {
    int i = blockIdx.x * 256 + threadIdx.x;
    if (i >= Cout * Ch) return;
    int o = i / Ch, c = i - o * Ch;
    float wl = W[(size_t)o * 2 * Ch + c];
    float wr = W[(size_t)o * 2 * Ch + Ch + c];
    out[(size_t)o * Ch + c] = wl;
    out[(size_t)(Cout + o) * Ch + c] = wr - wl;
}

// ---------------- batchnorm helpers ------------------------------------------
__global__ void zero_stats() {
    g_sum[threadIdx.x] = 0.f;
    g_sumsq[threadIdx.x] = 0.f;
}

__global__ void bn_stats(const float* __restrict__ x, int rpb, int C) {
    int c = threadIdx.x;
    const float* p = x + (size_t)blockIdx.x * rpb * C + c;
    float s = 0.f, ss = 0.f;
    for (int r = 0; r < rpb; r++) {
        float v = p[(size_t)r * C];
        s += v;
        ss += v * v;
    }
    atomicAdd(&g_sum[c], s);
    atomicAdd(&g_sumsq[c], ss);
}

__global__ void bn_finalize(float inv_n) {
    int c = threadIdx.x;
    float m = g_sum[c] * inv_n;
    float v = g_sumsq[c] * inv_n - m * m;
    g_mean[c] = m;
    g_rstd[c] = rsqrtf(v + 1e-5f);
}

__global__ void bn_apply(float* __restrict__ x, const float* __restrict__ gg,
                         const float* __restrict__ bb, int total, int cmask) {
    int i = blockIdx.x * 256 + threadIdx.x;
    if (i >= total) return;
    int c = i & cmask;
    float v = (x[i] - g_mean[c]) * g_rstd[c] * gg[c] + bb[c];
    x[i] = fmaxf(v, 0.f);
}

// ---------------- U/V implicit-group stats: rows are U[j]+V[n] ---------------
__global__ void uv_stats(const float* __restrict__ UV, const int* __restrict__ idx, int C) {
    int bn = blockIdx.x;
    int b = bn >> 10;
    const int* ip = idx + bn * 8;
    int j[8];
#pragma unroll
    for (int k = 0; k < 8; k++) j[k] = (b << 10) + ip[k];
    const size_t stride = (size_t)2 * C;
    const float* Vp = UV + (size_t)bn * stride + C;
    for (int c = threadIdx.x; c < C; c += blockDim.x) {
        float v = Vp[c];
        float s = 0.f, ss = 0.f;
#pragma unroll
        for (int k = 0; k < 8; k++) {
            float x = UV[(size_t)j[k] * stride + c] + v;
            s += x;
            ss += x * x;
        }
        atomicAdd(&g_sum[c], s);
        atomicAdd(&g_sumsq[c], ss);
    }
}

// combine U[j]+V[n], apply BN+ReLU -> dense activation (65536 x C)
__global__ void uv_combine(const float* __restrict__ UV, const int* __restrict__ idx,
                           const float* __restrict__ gg, const float* __restrict__ bb,
                           float* __restrict__ out, int clog, int total) {
    int i = blockIdx.x * 256 + threadIdx.x;
    if (i >= total) return;
    const int C = 1 << clog;
    int c = i & (C - 1);
    int row = i >> clog;
    int bn = row >> 3;
    int b = bn >> 10;
    int j = (b << 10) + idx[row];
    float u = UV[((size_t)j << (clog + 1)) + c];
    float v = UV[((size_t)bn << (clog + 1)) + C + c];
    float val = (u + v - g_mean[c]) * g_rstd[c] * gg[c] + bb[c];
    out[i] = fmaxf(val, 0.f);
}

// bn + relu + max over 8 neighbors -> out[bn, c]
__global__ void bn_apply_maxpool(const float* __restrict__ pre, const float* __restrict__ gg,
                                 const float* __restrict__ bb, float* __restrict__ out,
                                 int clog, int total) {
    int i = blockIdx.x * 256 + threadIdx.x;
    if (i >= total) return;
    int c = i & ((1 << clog) - 1);
    int bn = i >> clog;
    float m = g_mean[c], r = g_rstd[c] * gg[c], be = bb[c];
    const float* p = pre + (((size_t)bn * 8) << clog) + c;
    float best = 0.f;
#pragma unroll
    for (int k = 0; k < 8; k++) {
        float v = (p[(size_t)k << clog] - m) * r + be;
        best = fmaxf(best, v);
    }
    out[i] = best;
}

// final layer: transposed write out[b, c, n]
__global__ void bn_apply_maxpool_T(const float* __restrict__ pre, const float* __restrict__ gg,
                                   const float* __restrict__ bb, float* __restrict__ out) {
    int i = blockIdx.x * 256 + threadIdx.x;
    if (i >= 8192 * 1024) return;
    int c = i & 1023;
    int bn = i >> 10;
    int b = bn >> 10, n = bn & 1023;
    float m = g_mean[c], r = g_rstd[c] * gg[c], be = bb[c];
    const float* p = pre + (((size_t)bn * 8) << 10) + c;
    float best = 0.f;
#pragma unroll
    for (int k = 0; k < 8; k++) {
        float v = (p[(size_t)k << 10] - m) * r + be;
        best = fmaxf(best, v);
    }
    out[((((size_t)b << 10) | c) << 10) | n] = best;
}

// ---------------- kNN (k=8, includes self) ----------------------------------
__global__ void knn_kernel(const float* __restrict__ xyz, int* __restrict__ idx) {
    __shared__ float sx[1024], sy[1024], sz[1024], ssq[1024];
    int b = blockIdx.y;
    const float* base = xyz + b * 1024 * 3;
    for (int i = threadIdx.x; i < 1024; i += blockDim.x) {
        float x = base[i * 3 + 0], y = base[i * 3 + 1], z = base[i * 3 + 2];
        sx[i] = x; sy[i] = y; sz[i] = z;
        ssq[i] = x * x + y * y + z * z;
    }
    __syncthreads();
    int n = blockIdx.x * blockDim.x + threadIdx.x;
    float px = sx[n], py = sy[n], pz = sz[n], psq = ssq[n];
    float bd[8]; int bi[8];
#pragma unroll
    for (int s = 0; s < 8; s++) { bd[s] = 3.4e38f; bi[s] = 0; }
    int maxslot = 0;
    float worst = 3.4e38f;
    for (int j = 0; j < 1024; j++) {
        float d = (psq + ssq[j]) - 2.f * (px * sx[j] + py * sy[j] + pz * sz[j]);
        if (d < worst) {
#pragma unroll
            for (int s = 0; s < 8; s++) if (s == maxslot) { bd[s] = d; bi[s] = j; }
            worst = bd[0]; maxslot = 0;
#pragma unroll
            for (int s = 1; s < 8; s++) if (bd[s] > worst) { worst = bd[s]; maxslot = s; }
        }
    }
    int o = (b * 1024 + n) * 8;
#pragma unroll
    for (int s = 0; s < 8; s++) idx[o + s] = bi[s];
}

// ---------------- orchestration ---------------------------------------------
extern "C" void kernel_launch(void* const* d_in, const int* in_sizes, int n_in,
                              void* d_out, int out_size) {
    const float* xyz = (const float*)d_in[0];
    const float* W1  = (const float*)d_in[1];
    const float* g1  = (const float*)d_in[2];
    const float* b1  = (const float*)d_in[3];
    const float* W2  = (const float*)d_in[4];
    const float* g2  = (const float*)d_in[5];
    const float* b2  = (const float*)d_in[6];
    const float* WA1 = (const float*)d_in[7];
    const float* gA1 = (const float*)d_in[8];
    const float* bA1 = (const float*)d_in[9];
    const float* WA2 = (const float*)d_in[10];
    const float* gA2 = (const float*)d_in[11];
    const float* bA2 = (const float*)d_in[12];
    const float* WB1 = (const float*)d_in[13];
    const float* gB1 = (const float*)d_in[14];
    const float* bB1 = (const float*)d_in[15];
    const float* WB2 = (const float*)d_in[16];
    const float* gB2 = (const float*)d_in[17];
    const float* bB2 = (const float*)d_in[18];
    float* out = (float*)d_out;

    float *h1, *h2, *lA, *uv, *wcat, *bufA, *bufB;
    int* idx;
    cudaGetSymbolAddress((void**)&h1,   s_h1);
    cudaGetSymbolAddress((void**)&h2,   s_h2);
    cudaGetSymbolAddress((void**)&lA,   s_lA);
    cudaGetSymbolAddress((void**)&uv,   s_uv);
    cudaGetSymbolAddress((void**)&wcat, s_wcat);
    cudaGetSymbolAddress((void**)&bufA, s_bufA);
    cudaGetSymbolAddress((void**)&bufB, s_bufB);
    cudaGetSymbolAddress((void**)&idx,  s_idx);

    // ---- layer 1: 3 -> 64, BN+ReLU
    gemm_k3<<<(8192 * 64) / 256, 256>>>(xyz, W1, h1);
    zero_stats<<<1, 1024>>>();
    bn_stats<<<8192 / 32, 64>>>(h1, 32, 64);
    bn_finalize<<<1, 64>>>(1.f / 8192);
    bn_apply<<<(8192 * 64) / 256, 256>>>(h1, g1, b1, 8192 * 64, 63);

    // ---- layer 2: 64 -> 256, BN+ReLU (tensor)
    gemm_tf32<<<dim3(256 / 128, 8192 / 128), 256>>>(h1, W2, h2, 8192, 256, 64);
    zero_stats<<<1, 1024>>>();
    bn_stats<<<8192 / 32, 256>>>(h2, 32, 256);
    bn_finalize<<<1, 256>>>(1.f / 8192);
    bn_apply<<<(8192 * 256) / 256, 256>>>(h2, g2, b2, 8192 * 256, 255);

    // ---- kNN on xyz
    knn_kernel<<<dim3(4, 8), 256>>>(xyz, idx);

    // ===== stage A =====
    prep_wcat<<<(512 * 256 + 255) / 256, 256>>>(WA1, wcat, 512, 256);
    gemm_tf32<<<dim3(1024 / 128, 8192 / 128), 256>>>(h2, wcat, uv, 8192, 1024, 256);
    zero_stats<<<1, 1024>>>();
    uv_stats<<<8192, 256>>>(uv, idx, 512);
    bn_finalize<<<1, 512>>>(1.f / 65536);
    uv_combine<<<(65536 * 512) / 256, 256>>>(uv, idx, gA1, bA1, bufA, 9, 65536 * 512);

    gemm_tf32<<<dim3(512 / 128, 65536 / 128), 256>>>(bufA, WA2, bufB, 65536, 512, 512);
    zero_stats<<<1, 1024>>>();
    bn_stats<<<65536 / 64, 512>>>(bufB, 64, 512);
    bn_finalize<<<1, 512>>>(1.f / 65536);
    bn_apply_maxpool<<<(8192 * 512) / 256, 256>>>(bufB, gA2, bA2, lA, 9, 8192 * 512);

    // ===== stage B =====
    prep_wcat<<<(1024 * 512 + 255) / 256, 256>>>(WB1, wcat, 1024, 512);
    gemm_tf32<<<dim3(2048 / 128, 8192 / 128), 256>>>(lA, wcat, uv, 8192, 2048, 512);
    zero_stats<<<1, 1024>>>();
    uv_stats<<<8192, 256>>>(uv, idx, 1024);
    bn_finalize<<<1, 1024>>>(1.f / 65536);
    uv_combine<<<(65536 * 1024) / 256, 256>>>(uv, idx, gB1, bB1, bufA, 10, 65536 * 1024);

    gemm_tf32<<<dim3(1024 / 128, 65536 / 128), 256>>>(bufA, WB2, bufB, 65536, 1024, 1024);
    zero_stats<<<1, 1024>>>();
    bn_stats<<<65536 / 64, 1024>>>(bufB, 64, 1024);
    bn_finalize<<<1, 1024>>>(1.f / 65536);
    bn_apply_maxpool_T<<<(8192 * 1024) / 256, 256>>>(bufB, gB2, bB2, out);
}

// round 4
// speedup vs baseline: 2.6404x; 1.1135x over previous
#include <cuda_runtime.h>
#include <cuda_bf16.h>
#include <cstdint>

// ---------------- static scratch (allocation-free rule: __device__ globals) ----
__device__ float g_sum[1024];
__device__ float g_sumsq[1024];
__device__ float g_mean[1024];
__device__ float g_rstd[1024];

__device__ float s_h1[8192 * 64];
__device__ __nv_bfloat16 s_h1h[8192 * 64];
__device__ __nv_bfloat16 s_h1l[8192 * 64];
__device__ __nv_bfloat16 s_h2h[8192 * 256];
__device__ __nv_bfloat16 s_h2l[8192 * 256];
__device__ __nv_bfloat16 s_lAh[8192 * 512];
__device__ __nv_bfloat16 s_lAl[8192 * 512];
__device__ __nv_bfloat16 s_wh[1 << 21];          // weight hi (max 2048x512 / 1024x1024)
__device__ __nv_bfloat16 s_wl[1 << 21];          // weight lo
__device__ int   s_idx[8192 * 8];
__device__ float s_uv[8192 * 2048];              // U|V GEMM output (fp32)
__device__ __nv_bfloat16 s_aih[67108864];        // activation hi (65536 x 1024 max)
__device__ __nv_bfloat16 s_ail[67108864];        // activation lo
__device__ float s_bufB[67108864];               // GEMM outputs fp32 (65536 x 1024 max)

// ---------------- helpers -----------------------------------------------------
__device__ __forceinline__ void cp16(uint32_t dst, const void* src) {
    asm volatile("cp.async.ca.shared.global [%0], [%1], 16;\n" :: "r"(dst), "l"(src));
}
__device__ __forceinline__ void bsplit(float x, __nv_bfloat16& h, __nv_bfloat16& l) {
    h = __float2bfloat16(x);
    l = __float2bfloat16(x - __bfloat162float(h));
}
__device__ __forceinline__ void mma16816(float* d, const uint32_t* a, const uint32_t* b) {
    asm volatile(
        "mma.sync.aligned.m16n8k16.row.col.f32.bf16.bf16.f32 "
        "{%0,%1,%2,%3},{%4,%5,%6,%7},{%8,%9},{%0,%1,%2,%3};"
        : "+f"(d[0]), "+f"(d[1]), "+f"(d[2]), "+f"(d[3])
        : "r"(a[0]), "r"(a[1]), "r"(a[2]), "r"(a[3]), "r"(b[0]), "r"(b[1]));
}

// ================= bf16x2 split-precision NT GEMM ============================
// C[M,N] = (Ah+Al)[M,K] * (Bh+Bl)[N,K]^T  (drops Al*Bl; ~17-bit mantissa)
// Internally runs 3 K-segments: (Al,Bh), (Ah,Bl), (Ah,Bh).
// M%128==0, N%128==0, K%32==0
__global__ void __launch_bounds__(256) gemm_bf16x2(
        const __nv_bfloat16* __restrict__ Ah, const __nv_bfloat16* __restrict__ Al,
        const __nv_bfloat16* __restrict__ Bh, const __nv_bfloat16* __restrict__ Bl,
        float* __restrict__ C, int M, int N, int K) {
    constexpr int LDS = 40;                      // bf16 units; 80B row stride (conflict-free)
    __shared__ __align__(16) __nv_bfloat16 As[2][128][LDS];
    __shared__ __align__(16) __nv_bfloat16 Bs[2][128][LDS];
    const int tid = threadIdx.x, lane = tid & 31, wid = tid >> 5;
    const int bm = blockIdx.y * 128, bn = blockIdx.x * 128;
    const int wm = (wid & 3) * 32, wn = (wid >> 2) * 64;
    const int lr = tid >> 1, lc = (tid & 1) * 16;   // row, bf16-col base for cp.async

    float acc[2][8][4];
#pragma unroll
    for (int mi = 0; mi < 2; mi++)
#pragma unroll
        for (int ni = 0; ni < 8; ni++)
#pragma unroll
            for (int q = 0; q < 4; q++) acc[mi][ni][q] = 0.f;

    const int nk1 = K >> 5;          // 32-wide k-tiles per segment
    const int nkt = 3 * nk1;

    auto load_tile = [&](int t, int st) {
        const int s = t / nk1;
        const int k0 = (t - s * nk1) << 5;
        const __nv_bfloat16* Ab = ((s == 0) ? Al : Ah) + (size_t)(bm + lr) * K + k0 + lc;
        const __nv_bfloat16* Bb = ((s == 1) ? Bl : Bh) + (size_t)(bn + lr) * K + k0 + lc;
        cp16((uint32_t)__cvta_generic_to_shared(&As[st][lr][lc]),     Ab);
        cp16((uint32_t)__cvta_generic_to_shared(&As[st][lr][lc + 8]), Ab + 8);
        cp16((uint32_t)__cvta_generic_to_shared(&Bs[st][lr][lc]),     Bb);
        cp16((uint32_t)__cvta_generic_to_shared(&Bs[st][lr][lc + 8]), Bb + 8);
    };

    load_tile(0, 0);
    asm volatile("cp.async.commit_group;\n" ::: "memory");

    for (int t = 0; t < nkt; t++) {
        const int cur = t & 1, nxt = cur ^ 1;
        if (t + 1 < nkt) load_tile(t + 1, nxt);
        asm volatile("cp.async.commit_group;\n" ::: "memory");
        asm volatile("cp.async.wait_group 1;\n" ::: "memory");
        __syncthreads();

#pragma unroll
        for (int ks = 0; ks < 2; ks++) {
            const int k0 = ks * 16 + (lane & 3) * 2;
            uint32_t a[2][4], b[8][2];
            const int ar = wm + (lane >> 2);
#pragma unroll
            for (int mi = 0; mi < 2; mi++) {
                a[mi][0] = *(const uint32_t*)&As[cur][ar + mi * 16][k0];
                a[mi][1] = *(const uint32_t*)&As[cur][ar + mi * 16 + 8][k0];
                a[mi][2] = *(const uint32_t*)&As[cur][ar + mi * 16][k0 + 8];
                a[mi][3] = *(const uint32_t*)&As[cur][ar + mi * 16 + 8][k0 + 8];
            }
            const int br = wn + (lane >> 2);
#pragma unroll
            for (int ni = 0; ni < 8; ni++) {
                b[ni][0] = *(const uint32_t*)&Bs[cur][br + ni * 8][k0];
                b[ni][1] = *(const uint32_t*)&Bs[cur][br + ni * 8][k0 + 8];
            }
#pragma unroll
            for (int mi = 0; mi < 2; mi++)
#pragma unroll
                for (int ni = 0; ni < 8; ni++) mma16816(acc[mi][ni], a[mi], b[ni]);
        }
        __syncthreads();
    }

#pragma unroll
    for (int mi = 0; mi < 2; mi++)
#pragma unroll
        for (int ni = 0; ni < 8; ni++) {
            const int r0 = bm + wm + mi * 16 + (lane >> 2);
            const int c0 = bn + wn + ni * 8 + ((lane & 3) << 1);
            *(float2*)&C[(size_t)r0 * N + c0]       = make_float2(acc[mi][ni][0], acc[mi][ni][1]);
            *(float2*)&C[(size_t)(r0 + 8) * N + c0] = make_float2(acc[mi][ni][2], acc[mi][ni][3]);
        }
}

// ---------------- layer 1: xyz(8192x3) @ W1^T(3x64) -------------------------
__global__ void gemm_k3(const float* __restrict__ xyz, const float* __restrict__ W,
                        float* __restrict__ out) {
    int i = blockIdx.x * 256 + threadIdx.x;
    if (i >= 8192 * 64) return;
    int o = i & 63;
    int m = i >> 6;
    const float* x = xyz + m * 3;
    const float* w = W + o * 3;
    out[i] = x[0] * w[0] + x[1] * w[1] + x[2] * w[2];
}

// ---------------- weight prep: plain split -----------------------------------
__global__ void prep_w_split(const float* __restrict__ W, __nv_bfloat16* __restrict__ wh,
                             __nv_bfloat16* __restrict__ wl, int total) {
    int i = blockIdx.x * 256 + threadIdx.x;
    if (i >= total) return;
    bsplit(W[i], wh[i], wl[i]);
}

// ---------------- weight prep: [WL ; WR-WL] split ----------------------------
__global__ void prep_wcat_split(const float* __restrict__ W, __nv_bfloat16* __restrict__ wh,
                                __nv_bfloat16* __restrict__ wl, int Cout, int Ch) {
    int i = blockIdx.x * 256 + threadIdx.x;
    if (i >= Cout * Ch) return;
    int o = i / Ch, c = i - o * Ch;
    float a = W[(size_t)o * 2 * Ch + c];
    float r = W[(size_t)o * 2 * Ch + Ch + c];
    bsplit(a, wh[(size_t)o * Ch + c], wl[(size_t)o * Ch + c]);
    bsplit(r - a, wh[(size_t)(Cout + o) * Ch + c], wl[(size_t)(Cout + o) * Ch + c]);
}

// ---------------- batchnorm helpers ------------------------------------------
__global__ void zero_stats() {
    g_sum[threadIdx.x] = 0.f;
    g_sumsq[threadIdx.x] = 0.f;
}

__global__ void bn_stats(const float* __restrict__ x, int rpb, int C) {
    int c = threadIdx.x;                          // blockDim == C
    const float* p = x + (size_t)blockIdx.x * rpb * C + c;
    float s = 0.f, ss = 0.f;
    for (int r = 0; r < rpb; r++) {
        float v = p[(size_t)r * C];
        s += v;
        ss += v * v;
    }
    atomicAdd(&g_sum[c], s);
    atomicAdd(&g_sumsq[c], ss);
}

__global__ void bn_finalize(float inv_n) {
    int c = threadIdx.x;
    float m = g_sum[c] * inv_n;
    float v = g_sumsq[c] * inv_n - m * m;
    g_mean[c] = m;
    g_rstd[c] = rsqrtf(v + 1e-5f);
}

// BN+ReLU, write bf16 hi/lo split
__global__ void bn_apply_split(const float* __restrict__ x, const float* __restrict__ gg,
                               const float* __restrict__ bb, __nv_bfloat16* __restrict__ oh,
                               __nv_bfloat16* __restrict__ ol, int total, int cmask) {
    int i = blockIdx.x * 256 + threadIdx.x;
    if (i >= total) return;
    int c = i & cmask;
    float v = (x[i] - g_mean[c]) * g_rstd[c] * gg[c] + bb[c];
    bsplit(fmaxf(v, 0.f), oh[i], ol[i]);
}

// ---------------- U/V implicit-group stats (block-local accumulation) --------
__global__ void uv_stats(const float* __restrict__ UV, const int* __restrict__ idx, int C) {
    // 256 threads per block; each block handles 32 bn rows; thread owns channels
    // tid, tid+256, ... (C/256 <= 4)
    const int nc = C >> 8;
    float s[4] = {0.f, 0.f, 0.f, 0.f}, ss[4] = {0.f, 0.f, 0.f, 0.f};
    const int bn0 = blockIdx.x * 32;
    for (int r = 0; r < 32; r++) {
        const int bn = bn0 + r;
        const int b = bn >> 10;
        const int* ip = idx + bn * 8;
        int j[8];
#pragma unroll
        for (int k = 0; k < 8; k++) j[k] = (b << 10) + ip[k];
        const float* Vp = UV + (size_t)bn * 2 * C + C;
#pragma unroll 4
        for (int q = 0; q < nc; q++) {
            const int c = threadIdx.x + (q << 8);
            float v = Vp[c];
#pragma unroll
            for (int k = 0; k < 8; k++) {
                float x = UV[(size_t)j[k] * 2 * C + c] + v;
                s[q] += x;
                ss[q] += x * x;
            }
        }
    }
#pragma unroll 4
    for (int q = 0; q < nc; q++) {
        const int c = threadIdx.x + (q << 8);
        atomicAdd(&g_sum[c], s[q]);
        atomicAdd(&g_sumsq[c], ss[q]);
    }
}

// combine U[j]+V[n], BN+ReLU, write bf16 hi/lo (dense 65536 x C activation)
__global__ void uv_combine_split(const float* __restrict__ UV, const int* __restrict__ idx,
                                 const float* __restrict__ gg, const float* __restrict__ bb,
                                 __nv_bfloat16* __restrict__ oh, __nv_bfloat16* __restrict__ ol,
                                 int clog, int total) {
    int i = blockIdx.x * 256 + threadIdx.x;
    if (i >= total) return;
    const int C = 1 << clog;
    int c = i & (C - 1);
    int row = i >> clog;                 // bn*8 + k
    int bn = row >> 3;
    int b = bn >> 10;
    int j = (b << 10) + idx[row];
    float u = UV[((size_t)j << (clog + 1)) + c];
    float v = UV[((size_t)bn << (clog + 1)) + C + c];
    float val = (u + v - g_mean[c]) * g_rstd[c] * gg[c] + bb[c];
    bsplit(fmaxf(val, 0.f), oh[i], ol[i]);
}

// BN+ReLU+max over 8 neighbors, write bf16 hi/lo -> lA[bn, c]
__global__ void bn_apply_maxpool_split(const float* __restrict__ pre, const float* __restrict__ gg,
                                       const float* __restrict__ bb, __nv_bfloat16* __restrict__ oh,
                                       __nv_bfloat16* __restrict__ ol, int clog, int total) {
    int i = blockIdx.x * 256 + threadIdx.x;
    if (i >= total) return;
    int c = i & ((1 << clog) - 1);
    int bn = i >> clog;
    float m = g_mean[c], r = g_rstd[c] * gg[c], be = bb[c];
    const float* p = pre + (((size_t)bn * 8) << clog) + c;
    float best = 0.f;
#pragma unroll
    for (int k = 0; k < 8; k++) {
        float v = (p[(size_t)k << clog] - m) * r + be;
        best = fmaxf(best, v);
    }
    bsplit(best, oh[i], ol[i]);
}

// final layer: BN+ReLU+maxpool, transposed write out[b, c, n] (fp32)
__global__ void bn_apply_maxpool_T(const float* __restrict__ pre, const float* __restrict__ gg,
                                   const float* __restrict__ bb, float* __restrict__ out) {
    int i = blockIdx.x * 256 + threadIdx.x;
    if (i >= 8192 * 1024) return;
    int c = i & 1023;
    int bn = i >> 10;
    int b = bn >> 10, n = bn & 1023;
    float m = g_mean[c], r = g_rstd[c] * gg[c], be = bb[c];
    const float* p = pre + (((size_t)bn * 8) << 10) + c;
    float best = 0.f;
#pragma unroll
    for (int k = 0; k < 8; k++) {
        float v = (p[(size_t)k << 10] - m) * r + be;
        best = fmaxf(best, v);
    }
    out[((((size_t)b << 10) | c) << 10) | n] = best;
}

// ---------------- kNN (k=8, includes self) ----------------------------------
__global__ void knn_kernel(const float* __restrict__ xyz, int* __restrict__ idx) {
    __shared__ float sx[1024], sy[1024], sz[1024], ssq[1024];
    int b = blockIdx.y;
    const float* base = xyz + b * 1024 * 3;
    for (int i = threadIdx.x; i < 1024; i += blockDim.x) {
        float x = base[i * 3 + 0], y = base[i * 3 + 1], z = base[i * 3 + 2];
        sx[i] = x; sy[i] = y; sz[i] = z;
        ssq[i] = x * x + y * y + z * z;
    }
    __syncthreads();
    int n = blockIdx.x * blockDim.x + threadIdx.x;
    float px = sx[n], py = sy[n], pz = sz[n], psq = ssq[n];
    float bd[8]; int bi[8];
#pragma unroll
    for (int s = 0; s < 8; s++) { bd[s] = 3.4e38f; bi[s] = 0; }
    int maxslot = 0;
    float worst = 3.4e38f;
    for (int j = 0; j < 1024; j++) {
        float d = (psq + ssq[j]) - 2.f * (px * sx[j] + py * sy[j] + pz * sz[j]);
        if (d < worst) {
#pragma unroll
            for (int s = 0; s < 8; s++) if (s == maxslot) { bd[s] = d; bi[s] = j; }
            worst = bd[0]; maxslot = 0;
#pragma unroll
            for (int s = 1; s < 8; s++) if (bd[s] > worst) { worst = bd[s]; maxslot = s; }
        }
    }
    int o = (b * 1024 + n) * 8;
#pragma unroll
    for (int s = 0; s < 8; s++) idx[o + s] = bi[s];
}

// ---------------- orchestration ---------------------------------------------
extern "C" void kernel_launch(void* const* d_in, const int* in_sizes, int n_in,
                              void* d_out, int out_size) {
    const float* xyz = (const float*)d_in[0];
    const float* W1  = (const float*)d_in[1];
    const float* g1  = (const float*)d_in[2];
    const float* b1  = (const float*)d_in[3];
    const float* W2  = (const float*)d_in[4];
    const float* g2  = (const float*)d_in[5];
    const float* b2  = (const float*)d_in[6];
    const float* WA1 = (const float*)d_in[7];
    const float* gA1 = (const float*)d_in[8];
    const float* bA1 = (const float*)d_in[9];
    const float* WA2 = (const float*)d_in[10];
    const float* gA2 = (const float*)d_in[11];
    const float* bA2 = (const float*)d_in[12];
    const float* WB1 = (const float*)d_in[13];
    const float* gB1 = (const float*)d_in[14];
    const float* bB1 = (const float*)d_in[15];
    const float* WB2 = (const float*)d_in[16];
    const float* gB2 = (const float*)d_in[17];
    const float* bB2 = (const float*)d_in[18];
    float* out = (float*)d_out;

    float *h1, *uv, *bufB;
    __nv_bfloat16 *h1h, *h1l, *h2h, *h2l, *lAh, *lAl, *wh, *wl, *aih, *ail;
    int* idx;
    cudaGetSymbolAddress((void**)&h1,  s_h1);
    cudaGetSymbolAddress((void**)&h1h, s_h1h);
    cudaGetSymbolAddress((void**)&h1l, s_h1l);
    cudaGetSymbolAddress((void**)&h2h, s_h2h);
    cudaGetSymbolAddress((void**)&h2l, s_h2l);
    cudaGetSymbolAddress((void**)&lAh, s_lAh);
    cudaGetSymbolAddress((void**)&lAl, s_lAl);
    cudaGetSymbolAddress((void**)&wh,  s_wh);
    cudaGetSymbolAddress((void**)&wl,  s_wl);
    cudaGetSymbolAddress((void**)&uv,  s_uv);
    cudaGetSymbolAddress((void**)&aih, s_aih);
    cudaGetSymbolAddress((void**)&ail, s_ail);
    cudaGetSymbolAddress((void**)&bufB, s_bufB);
    cudaGetSymbolAddress((void**)&idx, s_idx);

    // ---- layer 1: 3 -> 64, BN+ReLU -> h1 split
    gemm_k3<<<(8192 * 64) / 256, 256>>>(xyz, W1, h1);
    zero_stats<<<1, 1024>>>();
    bn_stats<<<8192 / 256, 64>>>(h1, 256, 64);
    bn_finalize<<<1, 64>>>(1.f / 8192);
    bn_apply_split<<<(8192 * 64) / 256, 256>>>(h1, g1, b1, h1h, h1l, 8192 * 64, 63);

    // ---- layer 2: 64 -> 256 (bf16x2 tensor), BN+ReLU -> h2 split
    prep_w_split<<<(256 * 64 + 255) / 256, 256>>>(W2, wh, wl, 256 * 64);
    gemm_bf16x2<<<dim3(256 / 128, 8192 / 128), 256>>>(h1h, h1l, wh, wl, bufB, 8192, 256, 64);
    zero_stats<<<1, 1024>>>();
    bn_stats<<<8192 / 256, 256>>>(bufB, 256, 256);
    bn_finalize<<<1, 256>>>(1.f / 8192);
    bn_apply_split<<<(8192 * 256) / 256, 256>>>(bufB, g2, b2, h2h, h2l, 8192 * 256, 255);

    // ---- kNN on xyz
    knn_kernel<<<dim3(4, 8), 256>>>(xyz, idx);

    // ===== stage A =====
    // A1 restructured: UV(8192x1024) = h2 @ [WL; WR-WL]^T
    prep_wcat_split<<<(512 * 256 + 255) / 256, 256>>>(WA1, wh, wl, 512, 256);
    gemm_bf16x2<<<dim3(1024 / 128, 8192 / 128), 256>>>(h2h, h2l, wh, wl, uv, 8192, 1024, 256);
    zero_stats<<<1, 1024>>>();
    uv_stats<<<8192 / 32, 256>>>(uv, idx, 512);
    bn_finalize<<<1, 512>>>(1.f / 65536);
    uv_combine_split<<<(65536 * 512) / 256, 256>>>(uv, idx, gA1, bA1, aih, ail, 9, 65536 * 512);

    // A2: 65536x512 @ WA2^T, BN+ReLU+maxpool -> lA split
    prep_w_split<<<(512 * 512 + 255) / 256, 256>>>(WA2, wh, wl, 512 * 512);
    gemm_bf16x2<<<dim3(512 / 128, 65536 / 128), 256>>>(aih, ail, wh, wl, bufB, 65536, 512, 512);
    zero_stats<<<1, 1024>>>();
    bn_stats<<<65536 / 256, 512>>>(bufB, 256, 512);
    bn_finalize<<<1, 512>>>(1.f / 65536);
    bn_apply_maxpool_split<<<(8192 * 512) / 256, 256>>>(bufB, gA2, bA2, lAh, lAl, 9, 8192 * 512);

    // ===== stage B =====
    // B1 restructured: UV(8192x2048) = lA @ [WL; WR-WL]^T
    prep_wcat_split<<<(1024 * 512 + 255) / 256, 256>>>(WB1, wh, wl, 1024, 512);
    gemm_bf16x2<<<dim3(2048 / 128, 8192 / 128), 256>>>(lAh, lAl, wh, wl, uv, 8192, 2048, 512);
    zero_stats<<<1, 1024>>>();
    uv_stats<<<8192 / 32, 256>>>(uv, idx, 1024);
    bn_finalize<<<1, 1024>>>(1.f / 65536);
    uv_combine_split<<<(65536 * 1024) / 256, 256>>>(uv, idx, gB1, bB1, aih, ail, 10, 65536 * 1024);

    // B2: 65536x1024 @ WB2^T, BN+ReLU+maxpool, transposed write
    prep_w_split<<<(1024 * 1024 + 255) / 256, 256>>>(WB2, wh, wl, 1024 * 1024);
    gemm_bf16x2<<<dim3(1024 / 128, 65536 / 128), 256>>>(aih, ail, wh, wl, bufB, 65536, 1024, 1024);
    zero_stats<<<1, 1024>>>();
    bn_stats<<<65536 / 256, 1024>>>(bufB, 256, 1024);
    bn_finalize<<<1, 1024>>>(1.f / 65536);
    bn_apply_maxpool_T<<<(8192 * 1024) / 256, 256>>>(bufB, gB2, bB2, out);
}

// round 6
// speedup vs baseline: 3.1270x; 1.1843x over previous
#include <cuda_runtime.h>
#include <cuda_bf16.h>
#include <cstdint>

// ---------------- static scratch (allocation-free rule: __device__ globals) ----
__device__ float g_sum[1024];
__device__ float g_sumsq[1024];
__device__ float g_mean[1024];
__device__ float g_rstd[1024];

__device__ float s_h1[8192 * 64];
__device__ __nv_bfloat16 s_h1h[8192 * 64];
__device__ __nv_bfloat16 s_h1l[8192 * 64];
__device__ __nv_bfloat16 s_h2h[8192 * 256];
__device__ __nv_bfloat16 s_h2l[8192 * 256];
__device__ __nv_bfloat16 s_lAh[8192 * 512];
__device__ __nv_bfloat16 s_lAl[8192 * 512];
__device__ __nv_bfloat16 s_wh[1 << 21];
__device__ __nv_bfloat16 s_wl[1 << 21];
__device__ int   s_idx[8192 * 8];
__device__ float s_uv[8192 * 2048];
__device__ __nv_bfloat16 s_aih[67108864];
__device__ __nv_bfloat16 s_ail[67108864];
__device__ float s_bufB[67108864];

// ---------------- helpers -----------------------------------------------------
__device__ __forceinline__ void cp16(uint32_t dst, const void* src) {
    asm volatile("cp.async.ca.shared.global [%0], [%1], 16;\n" :: "r"(dst), "l"(src));
}
__device__ __forceinline__ void bsplit(float x, __nv_bfloat16& h, __nv_bfloat16& l) {
    h = __float2bfloat16(x);
    l = __float2bfloat16(x - __bfloat162float(h));
}
__device__ __forceinline__ uint32_t s2u(const void* p) {
    uint32_t a;
    asm("{ .reg .u64 t; cvta.to.shared.u64 t, %1; cvt.u32.u64 %0, t; }" : "=r"(a) : "l"(p));
    return a;
}
__device__ __forceinline__ void mma16816(float* d, const uint32_t* a, const uint32_t* b) {
    asm volatile(
        "mma.sync.aligned.m16n8k16.row.col.f32.bf16.bf16.f32 "
        "{%0,%1,%2,%3},{%4,%5,%6,%7},{%8,%9},{%0,%1,%2,%3};"
        : "+f"(d[0]), "+f"(d[1]), "+f"(d[2]), "+f"(d[3])
        : "r"(a[0]), "r"(a[1]), "r"(a[2]), "r"(a[3]), "r"(b[0]), "r"(b[1]));
}
__device__ __forceinline__ void ldm_x4(uint32_t& r0, uint32_t& r1, uint32_t& r2,
                                       uint32_t& r3, uint32_t addr) {
    asm volatile("ldmatrix.sync.aligned.m8n8.x4.shared.b16 {%0,%1,%2,%3}, [%4];"
                 : "=r"(r0), "=r"(r1), "=r"(r2), "=r"(r3) : "r"(addr));
}

// ================= bf16x2 split-precision NT GEMM (ldmatrix mainloop) ========
// C[M,N] = (Ah+Al)[M,K] * (Bh+Bl)[N,K]^T  (3 segments: AlBh, AhBl, AhBh)
// Block 128x128, warp tile 32x64, k-tile 32, double-buffered cp.async.
// M%128==0, N%128==0, K%32==0
__global__ void __launch_bounds__(256, 2) gemm_bf16x2(
        const __nv_bfloat16* __restrict__ Ah, const __nv_bfloat16* __restrict__ Al,
        const __nv_bfloat16* __restrict__ Bh, const __nv_bfloat16* __restrict__ Bl,
        float* __restrict__ C, int M, int N, int K) {
    constexpr int LDS = 40;                      // bf16 units; 80B row stride
    __shared__ __align__(16) __nv_bfloat16 As[2][128][LDS];
    __shared__ __align__(16) __nv_bfloat16 Bs[2][128][LDS];
    const int tid = threadIdx.x, lane = tid & 31, wid = tid >> 5;
    const int bm = blockIdx.y * 128, bn = blockIdx.x * 128;
    const int wm = (wid & 3) * 32, wn = (wid >> 2) * 64;
    const int lr = tid >> 1, lc = (tid & 1) * 16;

    float acc[2][8][4];
#pragma unroll
    for (int mi = 0; mi < 2; mi++)
#pragma unroll
        for (int ni = 0; ni < 8; ni++)
#pragma unroll
            for (int q = 0; q < 4; q++) acc[mi][ni][q] = 0.f;

    // per-lane ldmatrix base offsets (bf16 units within the [128][LDS] plane)
    const uint32_t aBase = s2u(&As[0][0][0]);
    const uint32_t bBase = s2u(&Bs[0][0][0]);
    const int aRow = wm + (lane & 15);
    const int aCol = (lane >> 4) << 3;           // 0 or 8
    const int g = lane >> 3;
    const int bRowOff = ((g >> 1) & 1) * 8 + (lane & 7);
    const int bCol = (g & 1) << 3;

    const int nk1 = K >> 5;
    const int nkt = 3 * nk1;

    auto load_tile = [&](int t, int st) {
        const int s = t / nk1;
        const int k0 = (t - s * nk1) << 5;
        const __nv_bfloat16* Ab = ((s == 0) ? Al : Ah) + (size_t)(bm + lr) * K + k0 + lc;
        const __nv_bfloat16* Bb = ((s == 1) ? Bl : Bh) + (size_t)(bn + lr) * K + k0 + lc;
        cp16((uint32_t)__cvta_generic_to_shared(&As[st][lr][lc]),     Ab);
        cp16((uint32_t)__cvta_generic_to_shared(&As[st][lr][lc + 8]), Ab + 8);
        cp16((uint32_t)__cvta_generic_to_shared(&Bs[st][lr][lc]),     Bb);
        cp16((uint32_t)__cvta_generic_to_shared(&Bs[st][lr][lc + 8]), Bb + 8);
    };

    load_tile(0, 0);
    asm volatile("cp.async.commit_group;\n" ::: "memory");

    for (int t = 0; t < nkt; t++) {
        const int cur = t & 1, nxt = cur ^ 1;
        if (t + 1 < nkt) load_tile(t + 1, nxt);
        asm volatile("cp.async.commit_group;\n" ::: "memory");
        asm volatile("cp.async.wait_group 1;\n" ::: "memory");
        __syncthreads();

        const uint32_t aPlane = aBase + (uint32_t)cur * 128 * LDS * 2;
        const uint32_t bPlane = bBase + (uint32_t)cur * 128 * LDS * 2;
#pragma unroll
        for (int ks = 0; ks < 2; ks++) {
            const int k0 = ks * 16;
            uint32_t a[2][4], b[8][2];
#pragma unroll
            for (int mi = 0; mi < 2; mi++)
                ldm_x4(a[mi][0], a[mi][1], a[mi][2], a[mi][3],
                       aPlane + ((uint32_t)(aRow + mi * 16) * LDS + k0 + aCol) * 2);
#pragma unroll
            for (int p = 0; p < 4; p++)
                ldm_x4(b[2 * p][0], b[2 * p][1], b[2 * p + 1][0], b[2 * p + 1][1],
                       bPlane + ((uint32_t)(wn + p * 16 + bRowOff) * LDS + k0 + bCol) * 2);
#pragma unroll
            for (int mi = 0; mi < 2; mi++)
#pragma unroll
                for (int ni = 0; ni < 8; ni++) mma16816(acc[mi][ni], a[mi], b[ni]);
        }
        __syncthreads();
    }

#pragma unroll
    for (int mi = 0; mi < 2; mi++)
#pragma unroll
        for (int ni = 0; ni < 8; ni++) {
            const int r0 = bm + wm + mi * 16 + (lane >> 2);
            const int c0 = bn + wn + ni * 8 + ((lane & 3) << 1);
            *(float2*)&C[(size_t)r0 * N + c0]       = make_float2(acc[mi][ni][0], acc[mi][ni][1]);
            *(float2*)&C[(size_t)(r0 + 8) * N + c0] = make_float2(acc[mi][ni][2], acc[mi][ni][3]);
        }
}

// ---------------- layer 1: xyz(8192x3) @ W1^T(3x64) -------------------------
__global__ void gemm_k3(const float* __restrict__ xyz, const float* __restrict__ W,
                        float* __restrict__ out) {
    int i = blockIdx.x * 256 + threadIdx.x;
    if (i >= 8192 * 64) return;
    int o = i & 63;
    int m = i >> 6;
    const float* x = xyz + m * 3;
    const float* w = W + o * 3;
    out[i] = x[0] * w[0] + x[1] * w[1] + x[2] * w[2];
}

// ---------------- weight prep ------------------------------------------------
__global__ void prep_w_split(const float* __restrict__ W, __nv_bfloat16* __restrict__ wh,
                             __nv_bfloat16* __restrict__ wl, int total) {
    int i = blockIdx.x * 256 + threadIdx.x;
    if (i >= total) return;
    bsplit(W[i], wh[i], wl[i]);
}

__global__ void prep_wcat_split(const float* __restrict__ W, __nv_bfloat16* __restrict__ wh,
                                __nv_bfloat16* __restrict__ wl, int Cout, int Ch) {
    int i = blockIdx.x * 256 + threadIdx.x;
    if (i >= Cout * Ch) return;
    int o = i / Ch, c = i - o * Ch;
    float a = W[(size_t)o * 2 * Ch + c];
    float r = W[(size_t)o * 2 * Ch + Ch + c];
    bsplit(a, wh[(size_t)o * Ch + c], wl[(size_t)o * Ch + c]);
    bsplit(r - a, wh[(size_t)(Cout + o) * Ch + c], wl[(size_t)(Cout + o) * Ch + c]);
}

// ---------------- batchnorm helpers ------------------------------------------
__global__ void zero_stats() {
    g_sum[threadIdx.x] = 0.f;
    g_sumsq[threadIdx.x] = 0.f;
}

__global__ void bn_stats(const float* __restrict__ x, int rpb, int C) {
    int c = threadIdx.x;
    const float* p = x + (size_t)blockIdx.x * rpb * C + c;
    float s = 0.f, ss = 0.f;
    for (int r = 0; r < rpb; r++) {
        float v = p[(size_t)r * C];
        s += v;
        ss += v * v;
    }
    atomicAdd(&g_sum[c], s);
    atomicAdd(&g_sumsq[c], ss);
}

__global__ void bn_finalize(float inv_n) {
    int c = threadIdx.x;
    float m = g_sum[c] * inv_n;
    float v = g_sumsq[c] * inv_n - m * m;
    g_mean[c] = m;
    g_rstd[c] = rsqrtf(v + 1e-5f);
}

__global__ void bn_apply_split(const float* __restrict__ x, const float* __restrict__ gg,
                               const float* __restrict__ bb, __nv_bfloat16* __restrict__ oh,
                               __nv_bfloat16* __restrict__ ol, int total, int cmask) {
    int i = blockIdx.x * 256 + threadIdx.x;
    if (i >= total) return;
    int c = i & cmask;
    float v = (x[i] - g_mean[c]) * g_rstd[c] * gg[c] + bb[c];
    bsplit(fmaxf(v, 0.f), oh[i], ol[i]);
}

// ---------------- U/V implicit-group stats -----------------------------------
__global__ void uv_stats(const float* __restrict__ UV, const int* __restrict__ idx, int C) {
    const int nc = C >> 8;
    float s[4] = {0.f, 0.f, 0.f, 0.f}, ss[4] = {0.f, 0.f, 0.f, 0.f};
    const int bn0 = blockIdx.x * 32;
    for (int r = 0; r < 32; r++) {
        const int bn = bn0 + r;
        const int b = bn >> 10;
        const int* ip = idx + bn * 8;
        int j[8];
#pragma unroll
        for (int k = 0; k < 8; k++) j[k] = (b << 10) + ip[k];
        const float* Vp = UV + (size_t)bn * 2 * C + C;
#pragma unroll 4
        for (int q = 0; q < nc; q++) {
            const int c = threadIdx.x + (q << 8);
            float v = Vp[c];
#pragma unroll
            for (int k = 0; k < 8; k++) {
                float x = UV[(size_t)j[k] * 2 * C + c] + v;
                s[q] += x;
                ss[q] += x * x;
            }
        }
    }
#pragma unroll 4
    for (int q = 0; q < nc; q++) {
        const int c = threadIdx.x + (q << 8);
        atomicAdd(&g_sum[c], s[q]);
        atomicAdd(&g_sumsq[c], ss[q]);
    }
}

__global__ void uv_combine_split(const float* __restrict__ UV, const int* __restrict__ idx,
                                 const float* __restrict__ gg, const float* __restrict__ bb,
                                 __nv_bfloat16* __restrict__ oh, __nv_bfloat16* __restrict__ ol,
                                 int clog, int total) {
    int i = blockIdx.x * 256 + threadIdx.x;
    if (i >= total) return;
    const int C = 1 << clog;
    int c = i & (C - 1);
    int row = i >> clog;
    int bn = row >> 3;
    int b = bn >> 10;
    int j = (b << 10) + idx[row];
    float u = UV[((size_t)j << (clog + 1)) + c];
    float v = UV[((size_t)bn << (clog + 1)) + C + c];
    float val = (u + v - g_mean[c]) * g_rstd[c] * gg[c] + bb[c];
    bsplit(fmaxf(val, 0.f), oh[i], ol[i]);
}

__global__ void bn_apply_maxpool_split(const float* __restrict__ pre, const float* __restrict__ gg,
                                       const float* __restrict__ bb, __nv_bfloat16* __restrict__ oh,
                                       __nv_bfloat16* __restrict__ ol, int clog, int total) {
    int i = blockIdx.x * 256 + threadIdx.x;
    if (i >= total) return;
    int c = i & ((1 << clog) - 1);
    int bn = i >> clog;
    float m = g_mean[c], r = g_rstd[c] * gg[c], be = bb[c];
    const float* p = pre + (((size_t)bn * 8) << clog) + c;
    float best = 0.f;
#pragma unroll
    for (int k = 0; k < 8; k++) {
        float v = (p[(size_t)k << clog] - m) * r + be;
        best = fmaxf(best, v);
    }
    bsplit(best, oh[i], ol[i]);
}

// final layer: BN+ReLU+maxpool + tiled transpose write out[b, c, n]
__global__ void bn_maxpool_T_tiled(const float* __restrict__ pre, const float* __restrict__ gg,
                                   const float* __restrict__ bb, float* __restrict__ out) {
    __shared__ float tile[32][33];
    const int b = blockIdx.z;
    const int c0 = blockIdx.y * 32;
    const int n0 = blockIdx.x * 32;
    const int tx = threadIdx.x, ty = threadIdx.y;      // (32, 8)
    const int c = c0 + tx;
    const float m = g_mean[c], rr = g_rstd[c] * gg[c], be = bb[c];
#pragma unroll
    for (int s = 0; s < 4; s++) {
        const int nl = ty + s * 8;
        const int bn = (b << 10) + n0 + nl;
        const float* p = pre + (((size_t)bn * 8) << 10) + c;
        float best = 0.f;
#pragma unroll
        for (int k = 0; k < 8; k++) {
            float v = (p[(size_t)k << 10] - m) * rr + be;
            best = fmaxf(best, v);
        }
        tile[nl][tx] = best;
    }
    __syncthreads();
#pragma unroll
    for (int s = 0; s < 4; s++) {
        const int cl = ty + s * 8;
        out[((((size_t)b << 10) | (c0 + cl)) << 10) | (n0 + tx)] = tile[tx][cl];
    }
}

// ---------------- kNN (k=8, includes self) ----------------------------------
__global__ void knn_kernel(const float* __restrict__ xyz, int* __restrict__ idx) {
    __shared__ float sx[1024], sy[1024], sz[1024], ssq[1024];
    int b = blockIdx.y;
    const float* base = xyz + b * 1024 * 3;
    for (int i = threadIdx.x; i < 1024; i += blockDim.x) {
        float x = base[i * 3 + 0], y = base[i * 3 + 1], z = base[i * 3 + 2];
        sx[i] = x; sy[i] = y; sz[i] = z;
        ssq[i] = x * x + y * y + z * z;
    }
    __syncthreads();
    int n = blockIdx.x * blockDim.x + threadIdx.x;
    float px = sx[n], py = sy[n], pz = sz[n], psq = ssq[n];
    float bd[8]; int bi[8];
#pragma unroll
    for (int s = 0; s < 8; s++) { bd[s] = 3.4e38f; bi[s] = 0; }
    int maxslot = 0;
    float worst = 3.4e38f;
    for (int j = 0; j < 1024; j++) {
        float d = (psq + ssq[j]) - 2.f * (px * sx[j] + py * sy[j] + pz * sz[j]);
        if (d < worst) {
#pragma unroll
            for (int s = 0; s < 8; s++) if (s == maxslot) { bd[s] = d; bi[s] = j; }
            worst = bd[0]; maxslot = 0;
#pragma unroll
            for (int s = 1; s < 8; s++) if (bd[s] > worst) { worst = bd[s]; maxslot = s; }
        }
    }
    int o = (b * 1024 + n) * 8;
#pragma unroll
    for (int s = 0; s < 8; s++) idx[o + s] = bi[s];
}

// ---------------- orchestration ---------------------------------------------
extern "C" void kernel_launch(void* const* d_in, const int* in_sizes, int n_in,
                              void* d_out, int out_size) {
    const float* xyz = (const float*)d_in[0];
    const float* W1  = (const float*)d_in[1];
    const float* g1  = (const float*)d_in[2];
    const float* b1  = (const float*)d_in[3];
    const float* W2  = (const float*)d_in[4];
    const float* g2  = (const float*)d_in[5];
    const float* b2  = (const float*)d_in[6];
    const float* WA1 = (const float*)d_in[7];
    const float* gA1 = (const float*)d_in[8];
    const float* bA1 = (const float*)d_in[9];
    const float* WA2 = (const float*)d_in[10];
    const float* gA2 = (const float*)d_in[11];
    const float* bA2 = (const float*)d_in[12];
    const float* WB1 = (const float*)d_in[13];
    const float* gB1 = (const float*)d_in[14];
    const float* bB1 = (const float*)d_in[15];
    const float* WB2 = (const float*)d_in[16];
    const float* gB2 = (const float*)d_in[17];
    const float* bB2 = (const float*)d_in[18];
    float* out = (float*)d_out;

    float *h1, *uv, *bufB;
    __nv_bfloat16 *h1h, *h1l, *h2h, *h2l, *lAh, *lAl, *wh, *wl, *aih, *ail;
    int* idx;
    cudaGetSymbolAddress((void**)&h1,  s_h1);
    cudaGetSymbolAddress((void**)&h1h, s_h1h);
    cudaGetSymbolAddress((void**)&h1l, s_h1l);
    cudaGetSymbolAddress((void**)&h2h, s_h2h);
    cudaGetSymbolAddress((void**)&h2l, s_h2l);
    cudaGetSymbolAddress((void**)&lAh, s_lAh);
    cudaGetSymbolAddress((void**)&lAl, s_lAl);
    cudaGetSymbolAddress((void**)&wh,  s_wh);
    cudaGetSymbolAddress((void**)&wl,  s_wl);
    cudaGetSymbolAddress((void**)&uv,  s_uv);
    cudaGetSymbolAddress((void**)&aih, s_aih);
    cudaGetSymbolAddress((void**)&ail, s_ail);
    cudaGetSymbolAddress((void**)&bufB, s_bufB);
    cudaGetSymbolAddress((void**)&idx, s_idx);

    // ---- layer 1: 3 -> 64, BN+ReLU -> h1 split
    gemm_k3<<<(8192 * 64) / 256, 256>>>(xyz, W1, h1);
    zero_stats<<<1, 1024>>>();
    bn_stats<<<8192 / 256, 64>>>(h1, 256, 64);
    bn_finalize<<<1, 64>>>(1.f / 8192);
    bn_apply_split<<<(8192 * 64) / 256, 256>>>(h1, g1, b1, h1h, h1l, 8192 * 64, 63);

    // ---- layer 2: 64 -> 256, BN+ReLU -> h2 split
    prep_w_split<<<(256 * 64 + 255) / 256, 256>>>(W2, wh, wl, 256 * 64);
    gemm_bf16x2<<<dim3(256 / 128, 8192 / 128), 256>>>(h1h, h1l, wh, wl, bufB, 8192, 256, 64);
    zero_stats<<<1, 1024>>>();
    bn_stats<<<8192 / 256, 256>>>(bufB, 256, 256);
    bn_finalize<<<1, 256>>>(1.f / 8192);
    bn_apply_split<<<(8192 * 256) / 256, 256>>>(bufB, g2, b2, h2h, h2l, 8192 * 256, 255);

    // ---- kNN on xyz
    knn_kernel<<<dim3(4, 8), 256>>>(xyz, idx);

    // ===== stage A =====
    prep_wcat_split<<<(512 * 256 + 255) / 256, 256>>>(WA1, wh, wl, 512, 256);
    gemm_bf16x2<<<dim3(1024 / 128, 8192 / 128), 256>>>(h2h, h2l, wh, wl, uv, 8192, 1024, 256);
    zero_stats<<<1, 1024>>>();
    uv_stats<<<8192 / 32, 256>>>(uv, idx, 512);
    bn_finalize<<<1, 512>>>(1.f / 65536);
    uv_combine_split<<<(65536 * 512) / 256, 256>>>(uv, idx, gA1, bA1, aih, ail, 9, 65536 * 512);

    prep_w_split<<<(512 * 512 + 255) / 256, 256>>>(WA2, wh, wl, 512 * 512);
    gemm_bf16x2<<<dim3(512 / 128, 65536 / 128), 256>>>(aih, ail, wh, wl, bufB, 65536, 512, 512);
    zero_stats<<<1, 1024>>>();
    bn_stats<<<65536 / 256, 512>>>(bufB, 256, 512);
    bn_finalize<<<1, 512>>>(1.f / 65536);
    bn_apply_maxpool_split<<<(8192 * 512) / 256, 256>>>(bufB, gA2, bA2, lAh, lAl, 9, 8192 * 512);

    // ===== stage B =====
    prep_wcat_split<<<(1024 * 512 + 255) / 256, 256>>>(WB1, wh, wl, 1024, 512);
    gemm_bf16x2<<<dim3(2048 / 128, 8192 / 128), 256>>>(lAh, lAl, wh, wl, uv, 8192, 2048, 512);
    zero_stats<<<1, 1024>>>();
    uv_stats<<<8192 / 32, 256>>>(uv, idx, 1024);
    bn_finalize<<<1, 1024>>>(1.f / 65536);
    uv_combine_split<<<(65536 * 1024) / 256, 256>>>(uv, idx, gB1, bB1, aih, ail, 10, 65536 * 1024);

    prep_w_split<<<(1024 * 1024 + 255) / 256, 256>>>(WB2, wh, wl, 1024 * 1024);
    gemm_bf16x2<<<dim3(1024 / 128, 65536 / 128), 256>>>(aih, ail, wh, wl, bufB, 65536, 1024, 1024);
    zero_stats<<<1, 1024>>>();
    bn_stats<<<65536 / 256, 1024>>>(bufB, 256, 1024);
    bn_finalize<<<1, 1024>>>(1.f / 65536);
    bn_maxpool_T_tiled<<<dim3(32, 32, 8), dim3(32, 8)>>>(bufB, gB2, bB2, out);
}

// round 7
// speedup vs baseline: 3.5973x; 1.1504x over previous
#include <cuda_runtime.h>
#include <cuda_bf16.h>
#include <cstdint>

// ---------------- static scratch (allocation-free rule: __device__ globals) ----
__device__ float g_sum[1024];
__device__ float g_sumsq[1024];
__device__ float g_mean[1024];
__device__ float g_rstd[1024];

__device__ float s_h1[8192 * 64];
__device__ __nv_bfloat16 s_h1h[8192 * 64];
__device__ __nv_bfloat16 s_h1l[8192 * 64];
__device__ __nv_bfloat16 s_h2h[8192 * 256];
__device__ __nv_bfloat16 s_h2l[8192 * 256];
__device__ __nv_bfloat16 s_lAh[8192 * 512];
__device__ __nv_bfloat16 s_lAl[8192 * 512];
__device__ __nv_bfloat16 s_wh[1 << 21];
__device__ __nv_bfloat16 s_wl[1 << 21];
__device__ int   s_idx[8192 * 8];
__device__ float s_uv[8192 * 2048];
__device__ __nv_bfloat16 s_aih[67108864];
__device__ __nv_bfloat16 s_ail[67108864];
__device__ float s_bufB[67108864];

// ---------------- helpers -----------------------------------------------------
__device__ __forceinline__ void cp16(uint32_t dst, const void* src) {
    asm volatile("cp.async.ca.shared.global [%0], [%1], 16;\n" :: "r"(dst), "l"(src));
}
__device__ __forceinline__ void bsplit(float x, __nv_bfloat16& h, __nv_bfloat16& l) {
    h = __float2bfloat16(x);
    l = __float2bfloat16(x - __bfloat162float(h));
}
__device__ __forceinline__ uint32_t s2u(const void* p) {
    uint32_t a;
    asm("{ .reg .u64 t; cvta.to.shared.u64 t, %1; cvt.u32.u64 %0, t; }" : "=r"(a) : "l"(p));
    return a;
}
__device__ __forceinline__ void mma16816(float* d, const uint32_t* a, const uint32_t* b) {
    asm volatile(
        "mma.sync.aligned.m16n8k16.row.col.f32.bf16.bf16.f32 "
        "{%0,%1,%2,%3},{%4,%5,%6,%7},{%8,%9},{%0,%1,%2,%3};"
        : "+f"(d[0]), "+f"(d[1]), "+f"(d[2]), "+f"(d[3])
        : "r"(a[0]), "r"(a[1]), "r"(a[2]), "r"(a[3]), "r"(b[0]), "r"(b[1]));
}
__device__ __forceinline__ void ldm_x4(uint32_t& r0, uint32_t& r1, uint32_t& r2,
                                       uint32_t& r3, uint32_t addr) {
    asm volatile("ldmatrix.sync.aligned.m8n8.x4.shared.b16 {%0,%1,%2,%3}, [%4];"
                 : "=r"(r0), "=r"(r1), "=r"(r2), "=r"(r3) : "r"(addr));
}

// ================= bf16x2 split-precision NT GEMM ============================
// C[M,N] = (Ah+Al)[M,K] * (Bh+Bl)[N,K]^T  (3 segments: AlBh, AhBl, AhBh)
// Block 128x128 with 4 warps (warp tile 64x64), k-tile 32, double-buffered.
// Optional fused BN-stats epilogue (per-channel sum/sumsq into g_sum/g_sumsq).
// M%128==0, N%128==0, K%32==0
__global__ void __launch_bounds__(128, 2) gemm_bf16x2(
        const __nv_bfloat16* __restrict__ Ah, const __nv_bfloat16* __restrict__ Al,
        const __nv_bfloat16* __restrict__ Bh, const __nv_bfloat16* __restrict__ Bl,
        float* __restrict__ C, int M, int N, int K, int do_stats) {
    constexpr int LDS = 40;                      // bf16 units; 80B row stride
    __shared__ __align__(16) __nv_bfloat16 As[2][128][LDS];
    __shared__ __align__(16) __nv_bfloat16 Bs[2][128][LDS];
    __shared__ float ssum[128], ssq[128];
    const int tid = threadIdx.x, lane = tid & 31, wid = tid >> 5;
    const int bm = blockIdx.y * 128, bn = blockIdx.x * 128;
    const int wm = (wid & 1) * 64, wn = (wid >> 1) * 64;

    float acc[4][8][4];
#pragma unroll
    for (int mi = 0; mi < 4; mi++)
#pragma unroll
        for (int ni = 0; ni < 8; ni++)
#pragma unroll
            for (int q = 0; q < 4; q++) acc[mi][ni][q] = 0.f;

    const uint32_t aBase = s2u(&As[0][0][0]);
    const uint32_t bBase = s2u(&Bs[0][0][0]);
    const int aRow = wm + (lane & 15);
    const int aCol = (lane >> 4) << 3;
    const int g = lane >> 3;
    const int bRowOff = ((g >> 1) & 1) * 8 + (lane & 7);
    const int bCol = (g & 1) << 3;

    const int lr = tid >> 2, lcc = (tid & 3) << 3;   // cp.async: row 0..31 base, col chunk

    const int nk1 = K >> 5;
    const int nkt = 3 * nk1;

    auto load_tile = [&](int t, int st) {
        const int s = t / nk1;
        const int k0 = (t - s * nk1) << 5;
        const __nv_bfloat16* Asrc = (s == 0) ? Al : Ah;
        const __nv_bfloat16* Bsrc = (s == 1) ? Bl : Bh;
#pragma unroll
        for (int q = 0; q < 4; q++) {
            const int row = lr + q * 32;
            cp16((uint32_t)__cvta_generic_to_shared(&As[st][row][lcc]),
                 Asrc + (size_t)(bm + row) * K + k0 + lcc);
            cp16((uint32_t)__cvta_generic_to_shared(&Bs[st][row][lcc]),
                 Bsrc + (size_t)(bn + row) * K + k0 + lcc);
        }
    };

    load_tile(0, 0);
    asm volatile("cp.async.commit_group;\n" ::: "memory");

    for (int t = 0; t < nkt; t++) {
        const int cur = t & 1, nxt = cur ^ 1;
        if (t + 1 < nkt) load_tile(t + 1, nxt);
        asm volatile("cp.async.commit_group;\n" ::: "memory");
        asm volatile("cp.async.wait_group 1;\n" ::: "memory");
        __syncthreads();

        const uint32_t aPlane = aBase + (uint32_t)cur * 128 * LDS * 2;
        const uint32_t bPlane = bBase + (uint32_t)cur * 128 * LDS * 2;
#pragma unroll
        for (int ks = 0; ks < 2; ks++) {
            const int k0 = ks * 16;
            uint32_t a[4][4], b[8][2];
#pragma unroll
            for (int mi = 0; mi < 4; mi++)
                ldm_x4(a[mi][0], a[mi][1], a[mi][2], a[mi][3],
                       aPlane + ((uint32_t)(aRow + mi * 16) * LDS + k0 + aCol) * 2);
#pragma unroll
            for (int p = 0; p < 4; p++)
                ldm_x4(b[2 * p][0], b[2 * p][1], b[2 * p + 1][0], b[2 * p + 1][1],
                       bPlane + ((uint32_t)(wn + p * 16 + bRowOff) * LDS + k0 + bCol) * 2);
#pragma unroll
            for (int mi = 0; mi < 4; mi++)
#pragma unroll
                for (int ni = 0; ni < 8; ni++) mma16816(acc[mi][ni], a[mi], b[ni]);
        }
        __syncthreads();
    }

    // ---- write C
#pragma unroll
    for (int mi = 0; mi < 4; mi++)
#pragma unroll
        for (int ni = 0; ni < 8; ni++) {
            const int r0 = bm + wm + mi * 16 + (lane >> 2);
            const int c0 = bn + wn + ni * 8 + ((lane & 3) << 1);
            *(float2*)&C[(size_t)r0 * N + c0]       = make_float2(acc[mi][ni][0], acc[mi][ni][1]);
            *(float2*)&C[(size_t)(r0 + 8) * N + c0] = make_float2(acc[mi][ni][2], acc[mi][ni][3]);
        }

    // ---- optional fused BN stats: per-channel sum / sumsq over this block's rows
    if (do_stats) {
        ssum[tid] = 0.f;
        ssq[tid] = 0.f;
        __syncthreads();
#pragma unroll
        for (int ni = 0; ni < 8; ni++)
#pragma unroll
            for (int par = 0; par < 2; par++) {
                float s = 0.f, sq = 0.f;
#pragma unroll
                for (int mi = 0; mi < 4; mi++) {
                    float v0 = acc[mi][ni][par], v1 = acc[mi][ni][par + 2];
                    s += v0 + v1;
                    sq += v0 * v0 + v1 * v1;
                }
                const int lc0 = wn + ni * 8 + ((lane & 3) << 1) + par;
                atomicAdd(&ssum[lc0], s);
                atomicAdd(&ssq[lc0], sq);
            }
        __syncthreads();
        atomicAdd(&g_sum[bn + tid], ssum[tid]);
        atomicAdd(&g_sumsq[bn + tid], ssq[tid]);
    }
}

// ---------------- layer 1: xyz(8192x3) @ W1^T(3x64) -------------------------
__global__ void gemm_k3(const float* __restrict__ xyz, const float* __restrict__ W,
                        float* __restrict__ out) {
    int i = blockIdx.x * 256 + threadIdx.x;
    if (i >= 8192 * 64) return;
    int o = i & 63;
    int m = i >> 6;
    const float* x = xyz + m * 3;
    const float* w = W + o * 3;
    out[i] = x[0] * w[0] + x[1] * w[1] + x[2] * w[2];
}

// ---------------- weight prep ------------------------------------------------
__global__ void prep_w_split(const float* __restrict__ W, __nv_bfloat16* __restrict__ wh,
                             __nv_bfloat16* __restrict__ wl, int total) {
    int i = blockIdx.x * 256 + threadIdx.x;
    if (i >= total) return;
    bsplit(W[i], wh[i], wl[i]);
}

__global__ void prep_wcat_split(const float* __restrict__ W, __nv_bfloat16* __restrict__ wh,
                                __nv_bfloat16* __restrict__ wl, int Cout, int Ch) {
    int i = blockIdx.x * 256 + threadIdx.x;
    if (i >= Cout * Ch) return;
    int o = i / Ch, c = i - o * Ch;
    float a = W[(size_t)o * 2 * Ch + c];
    float r = W[(size_t)o * 2 * Ch + Ch + c];
    bsplit(a, wh[(size_t)o * Ch + c], wl[(size_t)o * Ch + c]);
    bsplit(r - a, wh[(size_t)(Cout + o) * Ch + c], wl[(size_t)(Cout + o) * Ch + c]);
}

// ---------------- batchnorm helpers ------------------------------------------
__global__ void zero_stats() {
    g_sum[threadIdx.x] = 0.f;
    g_sumsq[threadIdx.x] = 0.f;
}

__global__ void bn_stats(const float* __restrict__ x, int rpb, int C) {
    int c = threadIdx.x;
    const float* p = x + (size_t)blockIdx.x * rpb * C + c;
    float s = 0.f, ss = 0.f;
    for (int r = 0; r < rpb; r++) {
        float v = p[(size_t)r * C];
        s += v;
        ss += v * v;
    }
    atomicAdd(&g_sum[c], s);
    atomicAdd(&g_sumsq[c], ss);
}

__global__ void bn_finalize(float inv_n) {
    int c = threadIdx.x;
    float m = g_sum[c] * inv_n;
    float v = g_sumsq[c] * inv_n - m * m;
    g_mean[c] = m;
    g_rstd[c] = rsqrtf(v + 1e-5f);
}

__global__ void bn_apply_split(const float* __restrict__ x, const float* __restrict__ gg,
                               const float* __restrict__ bb, __nv_bfloat16* __restrict__ oh,
                               __nv_bfloat16* __restrict__ ol, int total, int cmask) {
    int i = blockIdx.x * 256 + threadIdx.x;
    if (i >= total) return;
    int c = i & cmask;
    float v = (x[i] - g_mean[c]) * g_rstd[c] * gg[c] + bb[c];
    bsplit(fmaxf(v, 0.f), oh[i], ol[i]);
}

// ---------------- U/V implicit-group stats -----------------------------------
__global__ void uv_stats(const float* __restrict__ UV, const int* __restrict__ idx, int C) {
    const int nc = C >> 8;
    float s[4] = {0.f, 0.f, 0.f, 0.f}, ss[4] = {0.f, 0.f, 0.f, 0.f};
    const int bn0 = blockIdx.x * 32;
    for (int r = 0; r < 32; r++) {
        const int bn = bn0 + r;
        const int b = bn >> 10;
        const int* ip = idx + bn * 8;
        int j[8];
#pragma unroll
        for (int k = 0; k < 8; k++) j[k] = (b << 10) + ip[k];
        const float* Vp = UV + (size_t)bn * 2 * C + C;
#pragma unroll 4
        for (int q = 0; q < nc; q++) {
            const int c = threadIdx.x + (q << 8);
            float v = Vp[c];
#pragma unroll
            for (int k = 0; k < 8; k++) {
                float x = UV[(size_t)j[k] * 2 * C + c] + v;
                s[q] += x;
                ss[q] += x * x;
            }
        }
    }
#pragma unroll 4
    for (int q = 0; q < nc; q++) {
        const int c = threadIdx.x + (q << 8);
        atomicAdd(&g_sum[c], s[q]);
        atomicAdd(&g_sumsq[c], ss[q]);
    }
}

__global__ void uv_combine_split(const float* __restrict__ UV, const int* __restrict__ idx,
                                 const float* __restrict__ gg, const float* __restrict__ bb,
                                 __nv_bfloat16* __restrict__ oh, __nv_bfloat16* __restrict__ ol,
                                 int clog, int total) {
    int i = blockIdx.x * 256 + threadIdx.x;
    if (i >= total) return;
    const int C = 1 << clog;
    int c = i & (C - 1);
    int row = i >> clog;
    int bn = row >> 3;
    int b = bn >> 10;
    int j = (b << 10) + idx[row];
    float u = UV[((size_t)j << (clog + 1)) + c];
    float v = UV[((size_t)bn << (clog + 1)) + C + c];
    float val = (u + v - g_mean[c]) * g_rstd[c] * gg[c] + bb[c];
    bsplit(fmaxf(val, 0.f), oh[i], ol[i]);
}

__global__ void bn_apply_maxpool_split(const float* __restrict__ pre, const float* __restrict__ gg,
                                       const float* __restrict__ bb, __nv_bfloat16* __restrict__ oh,
                                       __nv_bfloat16* __restrict__ ol, int clog, int total) {
    int i = blockIdx.x * 256 + threadIdx.x;
    if (i >= total) return;
    int c = i & ((1 << clog) - 1);
    int bn = i >> clog;
    float m = g_mean[c], r = g_rstd[c] * gg[c], be = bb[c];
    const float* p = pre + (((size_t)bn * 8) << clog) + c;
    float best = 0.f;
#pragma unroll
    for (int k = 0; k < 8; k++) {
        float v = (p[(size_t)k << clog] - m) * r + be;
        best = fmaxf(best, v);
    }
    bsplit(best, oh[i], ol[i]);
}

// final layer: BN+ReLU+maxpool + tiled transpose write out[b, c, n]
__global__ void bn_maxpool_T_tiled(const float* __restrict__ pre, const float* __restrict__ gg,
                                   const float* __restrict__ bb, float* __restrict__ out) {
    __shared__ float tile[32][33];
    const int b = blockIdx.z;
    const int c0 = blockIdx.y * 32;
    const int n0 = blockIdx.x * 32;
    const int tx = threadIdx.x, ty = threadIdx.y;      // (32, 8)
    const int c = c0 + tx;
    const float m = g_mean[c], rr = g_rstd[c] * gg[c], be = bb[c];
#pragma unroll
    for (int s = 0; s < 4; s++) {
        const int nl = ty + s * 8;
        const int bn = (b << 10) + n0 + nl;
        const float* p = pre + (((size_t)bn * 8) << 10) + c;
        float best = 0.f;
#pragma unroll
        for (int k = 0; k < 8; k++) {
            float v = (p[(size_t)k << 10] - m) * rr + be;
            best = fmaxf(best, v);
        }
        tile[nl][tx] = best;
    }
    __syncthreads();
#pragma unroll
    for (int s = 0; s < 4; s++) {
        const int cl = ty + s * 8;
        out[((((size_t)b << 10) | (c0 + cl)) << 10) | (n0 + tx)] = tile[tx][cl];
    }
}

// ---------------- kNN (k=8, includes self) ----------------------------------
__global__ void knn_kernel(const float* __restrict__ xyz, int* __restrict__ idx) {
    __shared__ float sx[1024], sy[1024], sz[1024], ssq[1024];
    int b = blockIdx.y;
    const float* base = xyz + b * 1024 * 3;
    for (int i = threadIdx.x; i < 1024; i += blockDim.x) {
        float x = base[i * 3 + 0], y = base[i * 3 + 1], z = base[i * 3 + 2];
        sx[i] = x; sy[i] = y; sz[i] = z;
        ssq[i] = x * x + y * y + z * z;
    }
    __syncthreads();
    int n = blockIdx.x * blockDim.x + threadIdx.x;
    float px = sx[n], py = sy[n], pz = sz[n], psq = ssq[n];
    float bd[8]; int bi[8];
#pragma unroll
    for (int s = 0; s < 8; s++) { bd[s] = 3.4e38f; bi[s] = 0; }
    int maxslot = 0;
    float worst = 3.4e38f;
    for (int j = 0; j < 1024; j++) {
        float d = (psq + ssq[j]) - 2.f * (px * sx[j] + py * sy[j] + pz * sz[j]);
        if (d < worst) {
#pragma unroll
            for (int s = 0; s < 8; s++) if (s == maxslot) { bd[s] = d; bi[s] = j; }
            worst = bd[0]; maxslot = 0;
#pragma unroll
            for (int s = 1; s < 8; s++) if (bd[s] > worst) { worst = bd[s]; maxslot = s; }
        }
    }
    int o = (b * 1024 + n) * 8;
#pragma unroll
    for (int s = 0; s < 8; s++) idx[o + s] = bi[s];
}

// ---------------- orchestration ---------------------------------------------
extern "C" void kernel_launch(void* const* d_in, const int* in_sizes, int n_in,
                              void* d_out, int out_size) {
    const float* xyz = (const float*)d_in[0];
    const float* W1  = (const float*)d_in[1];
    const float* g1  = (const float*)d_in[2];
    const float* b1  = (const float*)d_in[3];
    const float* W2  = (const float*)d_in[4];
    const float* g2  = (const float*)d_in[5];
    const float* b2  = (const float*)d_in[6];
    const float* WA1 = (const float*)d_in[7];
    const float* gA1 = (const float*)d_in[8];
    const float* bA1 = (const float*)d_in[9];
    const float* WA2 = (const float*)d_in[10];
    const float* gA2 = (const float*)d_in[11];
    const float* bA2 = (const float*)d_in[12];
    const float* WB1 = (const float*)d_in[13];
    const float* gB1 = (const float*)d_in[14];
    const float* bB1 = (const float*)d_in[15];
    const float* WB2 = (const float*)d_in[16];
    const float* gB2 = (const float*)d_in[17];
    const float* bB2 = (const float*)d_in[18];
    float* out = (float*)d_out;

    float *h1, *uv, *bufB;
    __nv_bfloat16 *h1h, *h1l, *h2h, *h2l, *lAh, *lAl, *wh, *wl, *aih, *ail;
    int* idx;
    cudaGetSymbolAddress((void**)&h1,  s_h1);
    cudaGetSymbolAddress((void**)&h1h, s_h1h);
    cudaGetSymbolAddress((void**)&h1l, s_h1l);
    cudaGetSymbolAddress((void**)&h2h, s_h2h);
    cudaGetSymbolAddress((void**)&h2l, s_h2l);
    cudaGetSymbolAddress((void**)&lAh, s_lAh);
    cudaGetSymbolAddress((void**)&lAl, s_lAl);
    cudaGetSymbolAddress((void**)&wh,  s_wh);
    cudaGetSymbolAddress((void**)&wl,  s_wl);
    cudaGetSymbolAddress((void**)&uv,  s_uv);
    cudaGetSymbolAddress((void**)&aih, s_aih);
    cudaGetSymbolAddress((void**)&ail, s_ail);
    cudaGetSymbolAddress((void**)&bufB, s_bufB);
    cudaGetSymbolAddress((void**)&idx, s_idx);

    // ---- layer 1: 3 -> 64, BN+ReLU -> h1 split
    gemm_k3<<<(8192 * 64) / 256, 256>>>(xyz, W1, h1);
    zero_stats<<<1, 1024>>>();
    bn_stats<<<8192 / 256, 64>>>(h1, 256, 64);
    bn_finalize<<<1, 64>>>(1.f / 8192);
    bn_apply_split<<<(8192 * 64) / 256, 256>>>(h1, g1, b1, h1h, h1l, 8192 * 64, 63);

    // ---- layer 2: 64 -> 256, BN+ReLU -> h2 split (stats fused in GEMM)
    prep_w_split<<<(256 * 64 + 255) / 256, 256>>>(W2, wh, wl, 256 * 64);
    zero_stats<<<1, 1024>>>();
    gemm_bf16x2<<<dim3(256 / 128, 8192 / 128), 128>>>(h1h, h1l, wh, wl, bufB, 8192, 256, 64, 1);
    bn_finalize<<<1, 256>>>(1.f / 8192);
    bn_apply_split<<<(8192 * 256) / 256, 256>>>(bufB, g2, b2, h2h, h2l, 8192 * 256, 255);

    // ---- kNN on xyz
    knn_kernel<<<dim3(4, 8), 256>>>(xyz, idx);

    // ===== stage A =====
    prep_wcat_split<<<(512 * 256 + 255) / 256, 256>>>(WA1, wh, wl, 512, 256);
    gemm_bf16x2<<<dim3(1024 / 128, 8192 / 128), 128>>>(h2h, h2l, wh, wl, uv, 8192, 1024, 256, 0);
    zero_stats<<<1, 1024>>>();
    uv_stats<<<8192 / 32, 256>>>(uv, idx, 512);
    bn_finalize<<<1, 512>>>(1.f / 65536);
    uv_combine_split<<<(65536 * 512) / 256, 256>>>(uv, idx, gA1, bA1, aih, ail, 9, 65536 * 512);

    prep_w_split<<<(512 * 512 + 255) / 256, 256>>>(WA2, wh, wl, 512 * 512);
    zero_stats<<<1, 1024>>>();
    gemm_bf16x2<<<dim3(512 / 128, 65536 / 128), 128>>>(aih, ail, wh, wl, bufB, 65536, 512, 512, 1);
    bn_finalize<<<1, 512>>>(1.f / 65536);
    bn_apply_maxpool_split<<<(8192 * 512) / 256, 256>>>(bufB, gA2, bA2, lAh, lAl, 9, 8192 * 512);

    // ===== stage B =====
    prep_wcat_split<<<(1024 * 512 + 255) / 256, 256>>>(WB1, wh, wl, 1024, 512);
    gemm_bf16x2<<<dim3(2048 / 128, 8192 / 128), 128>>>(lAh, lAl, wh, wl, uv, 8192, 2048, 512, 0);
    zero_stats<<<1, 1024>>>();
    uv_stats<<<8192 / 32, 256>>>(uv, idx, 1024);
    bn_finalize<<<1, 1024>>>(1.f / 65536);
    uv_combine_split<<<(65536 * 1024) / 256, 256>>>(uv, idx, gB1, bB1, aih, ail, 10, 65536 * 1024);

    prep_w_split<<<(1024 * 1024 + 255) / 256, 256>>>(WB2, wh, wl, 1024 * 1024);
    zero_stats<<<1, 1024>>>();
    gemm_bf16x2<<<dim3(1024 / 128, 65536 / 128), 128>>>(aih, ail, wh, wl, bufB, 65536, 1024, 1024, 1);
    bn_finalize<<<1, 1024>>>(1.f / 65536);
    bn_maxpool_T_tiled<<<dim3(32, 32, 8), dim3(32, 8)>>>(bufB, gB2, bB2, out);
}